// round 12
// baseline (speedup 1.0000x reference)
#include <cuda_runtime.h>
#include <cuda_bf16.h>

#define NN 100000
#define NE 600000
#define ET (NE + NN)   // edges + self loops
#define H  128
#define NG 128
#define DIN 64
#define NB 391         // ceil(NN/256) scan blocks

// ---------------- scratch ----------------
__device__ float g_h[NN * H];
__device__ float g_xl[NN * H];
__device__ float g_xr[NN * H];
__device__ float g_pool[NG * H];
__device__ float g_cnt[NG];
__device__ int   g_deg[NN];
__device__ int   g_off[NN];
__device__ int   g_cursor[NN];
__device__ int   g_csrc[ET];
__device__ int   g_bsum[512];

// ---------------- helpers ----------------
__device__ __forceinline__ float lrelu(float v, float s) { return v > 0.f ? v : s * v; }

__device__ __forceinline__ void red_add_v4(float* p, float a, float b, float c, float d) {
    asm volatile("red.global.add.v4.f32 [%0], {%1,%2,%3,%4};"
                 :: "l"(p), "f"(a), "f"(b), "f"(c), "f"(d) : "memory");
}
__device__ __forceinline__ void red_add_f32(float* p, float a) {
    asm volatile("red.global.add.f32 [%0], %1;" :: "l"(p), "f"(a) : "memory");
}

__device__ __forceinline__ unsigned f2tf32(float x) {
    unsigned r;
    asm("cvt.rna.tf32.f32 %0, %1;" : "=r"(r) : "f"(x));
    return r;
}
// split fp32 into tf32 hi + tf32 lo (bit patterns stored as float)
__device__ __forceinline__ void tf32_split(float v, float& hi, float& lo) {
    unsigned h = f2tf32(v);
    hi = __uint_as_float(h);
    lo = __uint_as_float(f2tf32(v - hi));
}
__device__ __forceinline__ void mma_tf32(float c[4],
        unsigned a0, unsigned a1, unsigned a2, unsigned a3,
        unsigned b0, unsigned b1) {
    asm volatile("mma.sync.aligned.m16n8k8.row.col.f32.tf32.tf32.f32 "
        "{%0,%1,%2,%3}, {%4,%5,%6,%7}, {%8,%9}, {%0,%1,%2,%3};"
        : "+f"(c[0]), "+f"(c[1]), "+f"(c[2]), "+f"(c[3])
        : "r"(a0), "r"(a1), "r"(a2), "r"(a3), "r"(b0), "r"(b1));
}

// ---------------- CSR build ----------------
__global__ void k_init() {
    int i = blockIdx.x * blockDim.x + threadIdx.x;
    if (i < NN) g_deg[i] = 0;
    if (i < NG * H) g_pool[i] = 0.f;
    if (i < NG) g_cnt[i] = 0.f;
}
__global__ void k_hist(const int* __restrict__ ei) {
    int e = blockIdx.x * blockDim.x + threadIdx.x;
    if (e >= ET) return;
    int d = (e < NE) ? ei[NE + e] : (e - NE);
    atomicAdd(&g_deg[d], 1);
}
__global__ void k_scan1() {
    __shared__ int sm[256];
    int t = threadIdx.x;
    int i = blockIdx.x * 256 + t;
    int v = (i < NN) ? g_deg[i] : 0;
    sm[t] = v;
    __syncthreads();
    for (int o = 1; o < 256; o <<= 1) {
        int add = (t >= o) ? sm[t - o] : 0;
        __syncthreads();
        sm[t] += add;
        __syncthreads();
    }
    if (i < NN) g_off[i] = sm[t] - v;
    if (t == 255) g_bsum[blockIdx.x] = sm[255];
}
__global__ void k_scan2() {
    __shared__ int sm[512];
    int t = threadIdx.x;
    int v = (t < NB) ? g_bsum[t] : 0;
    sm[t] = v;
    __syncthreads();
    for (int o = 1; o < 512; o <<= 1) {
        int add = (t >= o) ? sm[t - o] : 0;
        __syncthreads();
        sm[t] += add;
        __syncthreads();
    }
    if (t < NB) g_bsum[t] = sm[t] - v;
}
__global__ void k_scan3() {
    int i = blockIdx.x * 256 + threadIdx.x;
    if (i >= NN) return;
    int o = g_off[i] + g_bsum[blockIdx.x];
    g_off[i] = o;
    g_cursor[i] = o;
}
__global__ void k_scatter(const int* __restrict__ ei) {
    int e = blockIdx.x * blockDim.x + threadIdx.x;
    if (e >= ET) return;
    int s, d;
    if (e < NE) { s = ei[e]; d = ei[NE + e]; }
    else        { s = e - NE; d = s; }
    int pos = atomicAdd(&g_cursor[d], 1);
    g_csrc[pos] = s;
}

// ---------------- TF32 tensor-core GEMM, smem-staged hi/lo (3xTF32) ----------------
// C = lrelu?(A[M,K] @ W[K,128] + bias); 256 thr = 8 warps, CTA tile 128x128,
// warp tile 32x64. K-chunk 16; hi/lo split done ONCE at staging; mainloop = LDS+MMA.
#define KC 16
#define AST 20    // As row stride (floats): g*20+th covers 32 distinct banks
#define WST 136   // Ws row stride

template<int K, bool DO_LRELU>
__global__ __launch_bounds__(256, 2) void k_gemm_mma(
    const float* __restrict__ A,
    const float* __restrict__ B0, const float* __restrict__ bias0, float* __restrict__ C0,
    const float* __restrict__ B1, const float* __restrict__ bias1, float* __restrict__ C1,
    int M)
{
    const float* Bw   = blockIdx.y ? B1 : B0;
    const float* bias = blockIdx.y ? bias1 : bias0;
    float*       C    = blockIdx.y ? C1 : C0;

    __shared__ float As_h[128][AST], As_l[128][AST];  // 2*10240 B
    __shared__ float Ws_h[KC][WST],  Ws_l[KC][WST];   // 2*8704 B   (total 37888 B)

    int tid  = threadIdx.x;
    int wid  = tid >> 5;
    int lane = tid & 31;
    int wr = wid & 3;            // m offset = 32*wr
    int wc = wid >> 2;           // n offset = 64*wc
    int row0 = blockIdx.x * 128;
    int g  = lane >> 2;          // groupID
    int th = lane & 3;           // thread-in-group

    // staging coords: A tile 128xKC (2 float4/thread), W tile KCx128 (2 float4/thread)
    int ar0 = tid >> 2,  ac = (tid & 3) << 2;      // +  ar0+... wait 128 rows: f>>2 gives 0..63 for i=0
    int wr0 = tid >> 5,  wcc = (tid & 31) << 2;

    const float4 z4 = make_float4(0.f, 0.f, 0.f, 0.f);
    float acc[2][8][4] = {};

    // prologue: load tile 0 into regs
    float4 pa[2], pw[2];
#pragma unroll
    for (int i = 0; i < 2; i++) {
        int r = ar0 + i * 64;
        int grow = row0 + r;
        pa[i] = (grow < M) ? *(const float4*)&A[(long)grow * K + ac] : z4;
        pw[i] = *(const float4*)&Bw[(long)(wr0 + i * 8) * 128 + wcc];
    }

    for (int k0 = 0; k0 < K; k0 += KC) {
        // store staged regs to smem with hi/lo split
#pragma unroll
        for (int i = 0; i < 2; i++) {
            int r = ar0 + i * 64;
            tf32_split(pa[i].x, As_h[r][ac + 0], As_l[r][ac + 0]);
            tf32_split(pa[i].y, As_h[r][ac + 1], As_l[r][ac + 1]);
            tf32_split(pa[i].z, As_h[r][ac + 2], As_l[r][ac + 2]);
            tf32_split(pa[i].w, As_h[r][ac + 3], As_l[r][ac + 3]);
            int rw = wr0 + i * 8;
            tf32_split(pw[i].x, Ws_h[rw][wcc + 0], Ws_l[rw][wcc + 0]);
            tf32_split(pw[i].y, Ws_h[rw][wcc + 1], Ws_l[rw][wcc + 1]);
            tf32_split(pw[i].z, Ws_h[rw][wcc + 2], Ws_l[rw][wcc + 2]);
            tf32_split(pw[i].w, Ws_h[rw][wcc + 3], Ws_l[rw][wcc + 3]);
        }
        __syncthreads();

        // prefetch next tile (LDG latency overlaps with MMA phase)
        int nk = k0 + KC;
        if (nk < K) {
#pragma unroll
            for (int i = 0; i < 2; i++) {
                int r = ar0 + i * 64;
                int grow = row0 + r;
                pa[i] = (grow < M) ? *(const float4*)&A[(long)grow * K + nk + ac] : z4;
                pw[i] = *(const float4*)&Bw[(long)(nk + wr0 + i * 8) * 128 + wcc];
            }
        }

        // mainloop: pure LDS + MMA
#pragma unroll
        for (int kk = 0; kk < KC; kk += 8) {
            unsigned ah[2][4], al[2][4];
#pragma unroll
            for (int mt = 0; mt < 2; mt++) {
                int mb = wr * 32 + mt * 16;
                ah[mt][0] = __float_as_uint(As_h[mb + g     ][kk + th    ]);
                ah[mt][1] = __float_as_uint(As_h[mb + g + 8 ][kk + th    ]);
                ah[mt][2] = __float_as_uint(As_h[mb + g     ][kk + th + 4]);
                ah[mt][3] = __float_as_uint(As_h[mb + g + 8 ][kk + th + 4]);
                al[mt][0] = __float_as_uint(As_l[mb + g     ][kk + th    ]);
                al[mt][1] = __float_as_uint(As_l[mb + g + 8 ][kk + th    ]);
                al[mt][2] = __float_as_uint(As_l[mb + g     ][kk + th + 4]);
                al[mt][3] = __float_as_uint(As_l[mb + g + 8 ][kk + th + 4]);
            }
#pragma unroll
            for (int nt = 0; nt < 8; nt++) {
                int nb = wc * 64 + nt * 8;
                unsigned bh0 = __float_as_uint(Ws_h[kk + th    ][nb + g]);
                unsigned bh1 = __float_as_uint(Ws_h[kk + th + 4][nb + g]);
                unsigned bl0 = __float_as_uint(Ws_l[kk + th    ][nb + g]);
                unsigned bl1 = __float_as_uint(Ws_l[kk + th + 4][nb + g]);
#pragma unroll
                for (int mt = 0; mt < 2; mt++) {
                    mma_tf32(acc[mt][nt], ah[mt][0], ah[mt][1], ah[mt][2], ah[mt][3], bh0, bh1);
                    mma_tf32(acc[mt][nt], al[mt][0], al[mt][1], al[mt][2], al[mt][3], bh0, bh1);
                    mma_tf32(acc[mt][nt], ah[mt][0], ah[mt][1], ah[mt][2], ah[mt][3], bl0, bl1);
                }
            }
        }
        __syncthreads();
    }

    // epilogue: bias + optional lrelu, float2 stores
#pragma unroll
    for (int nt = 0; nt < 8; nt++) {
        int col = wc * 64 + nt * 8 + 2 * th;
        float bx = bias[col], by = bias[col + 1];
#pragma unroll
        for (int mt = 0; mt < 2; mt++) {
            int r0 = row0 + wr * 32 + mt * 16 + g;
            float* c = acc[mt][nt];
            if (r0 < M) {
                float vx = c[0] + bx, vy = c[1] + by;
                if (DO_LRELU) { vx = lrelu(vx, 0.01f); vy = lrelu(vy, 0.01f); }
                *(float2*)&C[(long)r0 * 128 + col] = make_float2(vx, vy);
            }
            if (r0 + 8 < M) {
                float vx = c[2] + bx, vy = c[3] + by;
                if (DO_LRELU) { vx = lrelu(vx, 0.01f); vy = lrelu(vy, 0.01f); }
                *(float2*)&C[(long)(r0 + 8) * 128 + col] = make_float2(vx, vy);
            }
        }
    }
}

// ---------------- fused per-node edge kernel (CSR, no atomics) ----------------
template<bool POOL>
__global__ void k_node(const float* __restrict__ att, const float* __restrict__ bias,
                       const int* __restrict__ batch) {
    int node = (blockIdx.x * blockDim.x + threadIdx.x) >> 5;
    int lane = threadIdx.x & 31;
    if (node >= NN) return;

    int start = g_off[node];
    int deg   = g_deg[node];

    float4 xr4 = *(const float4*)&g_xr[node * H + lane * 4];
    float4 t4  = *(const float4*)&att[lane * 4];

    float4 acc = make_float4(0.f, 0.f, 0.f, 0.f);
    float denom = 0.f;

    for (int base = 0; base < deg; base += 32) {
        int m = min(32, deg - base);
        int s_l = (lane < m) ? g_csrc[start + base + lane] : 0;
#pragma unroll 4
        for (int j = 0; j < m; j++) {
            int s = __shfl_sync(0xffffffffu, s_l, j);
            float4 xl4 = *(const float4*)&g_xl[s * H + lane * 4];
            float e = t4.x * lrelu(xl4.x + xr4.x, 0.2f)
                    + t4.y * lrelu(xl4.y + xr4.y, 0.2f)
                    + t4.z * lrelu(xl4.z + xr4.z, 0.2f)
                    + t4.w * lrelu(xl4.w + xr4.w, 0.2f);
#pragma unroll
            for (int o = 16; o > 0; o >>= 1) e += __shfl_xor_sync(0xffffffffu, e, o);
            float a = __expf(e);
            denom += a;
            acc.x += a * xl4.x; acc.y += a * xl4.y;
            acc.z += a * xl4.z; acc.w += a * xl4.w;
        }
    }

    float inv = 1.0f / denom;        // self-loop guarantees denom > 0
    float4 b4 = *(const float4*)&bias[lane * 4];
    float vx = lrelu(acc.x * inv + b4.x, 0.01f);
    float vy = lrelu(acc.y * inv + b4.y, 0.01f);
    float vz = lrelu(acc.z * inv + b4.z, 0.01f);
    float vw = lrelu(acc.w * inv + b4.w, 0.01f);

    if (POOL) {
        int g = batch[node];
        red_add_v4(&g_pool[g * H + lane * 4], vx, vy, vz, vw);
        if (lane == 0) red_add_f32(&g_cnt[g], 1.0f);
    } else {
        *(float4*)&g_h[node * H + lane * 4] = make_float4(vx, vy, vz, vw);
    }
}

// head
__global__ void k_head(const float* __restrict__ W1, const float* __restrict__ b1,
                       const float* __restrict__ W2, const float* __restrict__ b2,
                       float* __restrict__ out) {
    int g = blockIdx.x;
    int t = threadIdx.x;
    __shared__ float hg[H];
    __shared__ float z[32];
    float c = fmaxf(g_cnt[g], 1.0f);
    for (int i = t; i < H; i += 32) hg[i] = g_pool[g * H + i] / c;
    __syncthreads();
    float acc = b1[t];
#pragma unroll 8
    for (int k = 0; k < H; k++) acc += hg[k] * W1[k * 32 + t];
    z[t] = lrelu(acc, 0.01f);
    __syncthreads();
    if (t < 16) {
        float o = b2[t];
#pragma unroll
        for (int k = 0; k < 32; k++) o += z[k] * W2[k * 16 + t];
        out[g * 16 + t] = o;
    }
}

// ---------------- launch ----------------
extern "C" void kernel_launch(void* const* d_in, const int* in_sizes, int n_in,
                              void* d_out, int out_size) {
    const float* x      = (const float*)d_in[0];
    const int*   ei     = (const int*)d_in[1];
    const int*   batch  = (const int*)d_in[2];
    const float* W_nfc  = (const float*)d_in[3];
    const float* b_nfc  = (const float*)d_in[4];
    const float* Wl1    = (const float*)d_in[5];
    const float* bl1    = (const float*)d_in[6];
    const float* Wr1    = (const float*)d_in[7];
    const float* br1    = (const float*)d_in[8];
    const float* att1   = (const float*)d_in[9];
    const float* bias1  = (const float*)d_in[10];
    const float* Wl2    = (const float*)d_in[11];
    const float* bl2    = (const float*)d_in[12];
    const float* Wr2    = (const float*)d_in[13];
    const float* br2    = (const float*)d_in[14];
    const float* att2   = (const float*)d_in[15];
    const float* bias2  = (const float*)d_in[16];
    const float* W_fc1  = (const float*)d_in[17];
    const float* b_fc1  = (const float*)d_in[18];
    const float* W_fc2  = (const float*)d_in[19];
    const float* b_fc2  = (const float*)d_in[20];
    float*       out    = (float*)d_out;

    float* gh  = nullptr; cudaGetSymbolAddress((void**)&gh,  g_h);
    float* gxl = nullptr; cudaGetSymbolAddress((void**)&gxl, g_xl);
    float* gxr = nullptr; cudaGetSymbolAddress((void**)&gxr, g_xr);

    static cudaStream_t s2 = nullptr;
    static cudaEvent_t  evF = nullptr, evJ = nullptr;
    if (s2 == nullptr) {
        cudaStreamCreateWithFlags(&s2, cudaStreamNonBlocking);
        cudaEventCreateWithFlags(&evF, cudaEventDisableTiming);
        cudaEventCreateWithFlags(&evJ, cudaEventDisableTiming);
    }

    const int MB  = (NN + 127) / 128;             // 782
    const int ETB = (ET + 255) / 256;
    const int NWB = (NN * 32 + 255) / 256;

    // fork: CSR build on s2, GEMM chain on capture stream
    cudaEventRecord(evF, 0);
    cudaStreamWaitEvent(s2, evF, 0);

    k_init<<<NB, 256, 0, s2>>>();
    k_hist<<<ETB, 256, 0, s2>>>(ei);
    k_scan1<<<NB, 256, 0, s2>>>();
    k_scan2<<<1, 512, 0, s2>>>();
    k_scan3<<<NB, 256, 0, s2>>>();
    k_scatter<<<ETB, 256, 0, s2>>>(ei);
    cudaEventRecord(evJ, s2);

    // nfc + layer-1 linear (tensor cores)
    k_gemm_mma<DIN, true><<<dim3(MB, 1), 256>>>(x, W_nfc, b_nfc, gh, W_nfc, b_nfc, gh, NN);
    k_gemm_mma<H, false><<<dim3(MB, 2), 256>>>(gh, Wl1, bl1, gxl, Wr1, br1, gxr, NN);

    // join CSR
    cudaStreamWaitEvent(0, evJ, 0);

    k_node<false><<<NWB, 256>>>(att1, bias1, batch);

    k_gemm_mma<H, false><<<dim3(MB, 2), 256>>>(gh, Wl2, bl2, gxl, Wr2, br2, gxr, NN);
    k_node<true><<<NWB, 256>>>(att2, bias2, batch);

    k_head<<<NG, 32>>>(W_fc1, b_fc1, W_fc2, b_fc2, out);
}

// round 13
// speedup vs baseline: 1.0426x; 1.0426x over previous
#include <cuda_runtime.h>
#include <cuda_bf16.h>

#define NN 100000
#define NE 600000
#define ET (NE + NN)   // edges + self loops
#define H  128
#define NG 128
#define DIN 64
#define NB 391         // ceil(NN/256) scan blocks

// ---------------- scratch ----------------
__device__ float g_h[NN * H];
__device__ float g_xl[NN * H];
__device__ float g_xr[NN * H];
__device__ float g_pool[NG * H];
__device__ float g_cnt[NG];
__device__ int   g_deg[NN];
__device__ int   g_off[NN];
__device__ int   g_cursor[NN];
__device__ int   g_csrc[ET];
__device__ int   g_bsum[512];

// ---------------- helpers ----------------
__device__ __forceinline__ float lrelu(float v, float s) { return v > 0.f ? v : s * v; }

__device__ __forceinline__ void red_add_v4(float* p, float a, float b, float c, float d) {
    asm volatile("red.global.add.v4.f32 [%0], {%1,%2,%3,%4};"
                 :: "l"(p), "f"(a), "f"(b), "f"(c), "f"(d) : "memory");
}
__device__ __forceinline__ void red_add_f32(float* p, float a) {
    asm volatile("red.global.add.f32 [%0], %1;" :: "l"(p), "f"(a) : "memory");
}

__device__ __forceinline__ unsigned f2tf32(float x) {
    unsigned r;
    asm("cvt.rna.tf32.f32 %0, %1;" : "=r"(r) : "f"(x));
    return r;
}
__device__ __forceinline__ void mma_tf32(float c[4],
        unsigned a0, unsigned a1, unsigned a2, unsigned a3,
        unsigned b0, unsigned b1) {
    asm volatile("mma.sync.aligned.m16n8k8.row.col.f32.tf32.tf32.f32 "
        "{%0,%1,%2,%3}, {%4,%5,%6,%7}, {%8,%9}, {%0,%1,%2,%3};"
        : "+f"(c[0]), "+f"(c[1]), "+f"(c[2]), "+f"(c[3])
        : "r"(a0), "r"(a1), "r"(a2), "r"(a3), "r"(b0), "r"(b1));
}

// ---------------- CSR build ----------------
__global__ void k_init() {
    int i = blockIdx.x * blockDim.x + threadIdx.x;
    if (i < NN) g_deg[i] = 0;
    if (i < NG * H) g_pool[i] = 0.f;
    if (i < NG) g_cnt[i] = 0.f;
}
__global__ void k_hist(const int* __restrict__ ei) {
    int e = blockIdx.x * blockDim.x + threadIdx.x;
    if (e >= ET) return;
    int d = (e < NE) ? ei[NE + e] : (e - NE);
    atomicAdd(&g_deg[d], 1);
}
__global__ void k_scan1() {
    __shared__ int sm[256];
    int t = threadIdx.x;
    int i = blockIdx.x * 256 + t;
    int v = (i < NN) ? g_deg[i] : 0;
    sm[t] = v;
    __syncthreads();
    for (int o = 1; o < 256; o <<= 1) {
        int add = (t >= o) ? sm[t - o] : 0;
        __syncthreads();
        sm[t] += add;
        __syncthreads();
    }
    if (i < NN) g_off[i] = sm[t] - v;
    if (t == 255) g_bsum[blockIdx.x] = sm[255];
}
__global__ void k_scan2() {
    __shared__ int sm[512];
    int t = threadIdx.x;
    int v = (t < NB) ? g_bsum[t] : 0;
    sm[t] = v;
    __syncthreads();
    for (int o = 1; o < 512; o <<= 1) {
        int add = (t >= o) ? sm[t - o] : 0;
        __syncthreads();
        sm[t] += add;
        __syncthreads();
    }
    if (t < NB) g_bsum[t] = sm[t] - v;
}
__global__ void k_scan3() {
    int i = blockIdx.x * 256 + threadIdx.x;
    if (i >= NN) return;
    int o = g_off[i] + g_bsum[blockIdx.x];
    g_off[i] = o;
    g_cursor[i] = o;
}
__global__ void k_scatter(const int* __restrict__ ei) {
    int e = blockIdx.x * blockDim.x + threadIdx.x;
    if (e >= ET) return;
    int s, d;
    if (e < NE) { s = ei[e]; d = ei[NE + e]; }
    else        { s = e - NE; d = s; }
    int pos = atomicAdd(&g_cursor[d], 1);
    g_csrc[pos] = s;
}

// ---------------- TF32 tensor-core GEMM (3xTF32, inline splits — R10 proven) ----------------
#define APAD 36
#define WPAD 136

template<int K, bool DO_LRELU>
__global__ __launch_bounds__(256, 2) void k_gemm_mma(
    const float* __restrict__ A,
    const float* __restrict__ B0, const float* __restrict__ bias0, float* __restrict__ C0,
    const float* __restrict__ B1, const float* __restrict__ bias1, float* __restrict__ C1,
    int M)
{
    const float* Bw   = blockIdx.y ? B1 : B0;
    const float* bias = blockIdx.y ? bias1 : bias0;
    float*       C    = blockIdx.y ? C1 : C0;

    __shared__ float As[128][APAD];   // 18432 B
    __shared__ float Ws[32][WPAD];    // 17408 B

    int tid  = threadIdx.x;
    int wid  = tid >> 5;
    int lane = tid & 31;
    int wr = wid & 3;            // m offset = 32*wr
    int wc = wid >> 2;           // n offset = 64*wc
    int row0 = blockIdx.x * 128;
    int g  = lane >> 2;          // groupID
    int th = lane & 3;           // thread-in-group

    const float4 z4 = make_float4(0.f, 0.f, 0.f, 0.f);
    float acc[2][8][4] = {};

    for (int k0 = 0; k0 < K; k0 += 32) {
        // stage A tile 128x32 (each thread: 4 float4)
#pragma unroll
        for (int i = 0; i < 4; i++) {
            int f = tid + i * 256;
            int r = f >> 3, c = (f & 7) << 2;
            int grow = row0 + r;
            float4 v = (grow < M) ? *(const float4*)&A[(long)grow * K + k0 + c] : z4;
            *(float4*)&As[r][c] = v;
        }
        // stage W tile 32x128
#pragma unroll
        for (int i = 0; i < 4; i++) {
            int f = tid + i * 256;
            int r = f >> 5, c = (f & 31) << 2;
            *(float4*)&Ws[r][c] = *(const float4*)&Bw[(long)(k0 + r) * 128 + c];
        }
        __syncthreads();

#pragma unroll
        for (int kk = 0; kk < 32; kk += 8) {
            unsigned ah[2][4], al[2][4];
#pragma unroll
            for (int mt = 0; mt < 2; mt++) {
                int mb = wr * 32 + mt * 16;
                float a0 = As[mb + g     ][kk + th];
                float a1 = As[mb + g + 8 ][kk + th];
                float a2 = As[mb + g     ][kk + th + 4];
                float a3 = As[mb + g + 8 ][kk + th + 4];
                ah[mt][0] = f2tf32(a0); al[mt][0] = f2tf32(a0 - __uint_as_float(ah[mt][0]));
                ah[mt][1] = f2tf32(a1); al[mt][1] = f2tf32(a1 - __uint_as_float(ah[mt][1]));
                ah[mt][2] = f2tf32(a2); al[mt][2] = f2tf32(a2 - __uint_as_float(ah[mt][2]));
                ah[mt][3] = f2tf32(a3); al[mt][3] = f2tf32(a3 - __uint_as_float(ah[mt][3]));
            }
#pragma unroll
            for (int nt = 0; nt < 8; nt++) {
                int nb = wc * 64 + nt * 8;
                float b0f = Ws[kk + th    ][nb + g];
                float b1f = Ws[kk + th + 4][nb + g];
                unsigned bh0 = f2tf32(b0f), bl0 = f2tf32(b0f - __uint_as_float(bh0));
                unsigned bh1 = f2tf32(b1f), bl1 = f2tf32(b1f - __uint_as_float(bh1));
#pragma unroll
                for (int mt = 0; mt < 2; mt++) {
                    mma_tf32(acc[mt][nt], ah[mt][0], ah[mt][1], ah[mt][2], ah[mt][3], bh0, bh1);
                    mma_tf32(acc[mt][nt], al[mt][0], al[mt][1], al[mt][2], al[mt][3], bh0, bh1);
                    mma_tf32(acc[mt][nt], ah[mt][0], ah[mt][1], ah[mt][2], ah[mt][3], bl0, bl1);
                }
            }
        }
        __syncthreads();
    }

    // epilogue: bias + optional lrelu, float2 stores
#pragma unroll
    for (int nt = 0; nt < 8; nt++) {
        int col = wc * 64 + nt * 8 + 2 * th;
        float bx = bias[col], by = bias[col + 1];
#pragma unroll
        for (int mt = 0; mt < 2; mt++) {
            int r0 = row0 + wr * 32 + mt * 16 + g;
            float* c = acc[mt][nt];
            if (r0 < M) {
                float vx = c[0] + bx, vy = c[1] + by;
                if (DO_LRELU) { vx = lrelu(vx, 0.01f); vy = lrelu(vy, 0.01f); }
                *(float2*)&C[(long)r0 * 128 + col] = make_float2(vx, vy);
            }
            if (r0 + 8 < M) {
                float vx = c[2] + bx, vy = c[3] + by;
                if (DO_LRELU) { vx = lrelu(vx, 0.01f); vy = lrelu(vy, 0.01f); }
                *(float2*)&C[(long)(r0 + 8) * 128 + col] = make_float2(vx, vy);
            }
        }
    }
}

// ---------------- fused per-node edge kernel (CSR, no atomics) ----------------
template<bool POOL>
__global__ void k_node(const float* __restrict__ att, const float* __restrict__ bias,
                       const int* __restrict__ batch) {
    int node = (blockIdx.x * blockDim.x + threadIdx.x) >> 5;
    int lane = threadIdx.x & 31;
    if (node >= NN) return;

    int start = g_off[node];
    int deg   = g_deg[node];

    float4 xr4 = *(const float4*)&g_xr[node * H + lane * 4];
    float4 t4  = *(const float4*)&att[lane * 4];

    float4 acc = make_float4(0.f, 0.f, 0.f, 0.f);
    float denom = 0.f;

    for (int base = 0; base < deg; base += 32) {
        int m = min(32, deg - base);
        int s_l = (lane < m) ? g_csrc[start + base + lane] : 0;
#pragma unroll 4
        for (int j = 0; j < m; j++) {
            int s = __shfl_sync(0xffffffffu, s_l, j);
            float4 xl4 = *(const float4*)&g_xl[s * H + lane * 4];
            float e = t4.x * lrelu(xl4.x + xr4.x, 0.2f)
                    + t4.y * lrelu(xl4.y + xr4.y, 0.2f)
                    + t4.z * lrelu(xl4.z + xr4.z, 0.2f)
                    + t4.w * lrelu(xl4.w + xr4.w, 0.2f);
#pragma unroll
            for (int o = 16; o > 0; o >>= 1) e += __shfl_xor_sync(0xffffffffu, e, o);
            float a = __expf(e);
            denom += a;
            acc.x += a * xl4.x; acc.y += a * xl4.y;
            acc.z += a * xl4.z; acc.w += a * xl4.w;
        }
    }

    float inv = 1.0f / denom;        // self-loop guarantees denom > 0
    float4 b4 = *(const float4*)&bias[lane * 4];
    float vx = lrelu(acc.x * inv + b4.x, 0.01f);
    float vy = lrelu(acc.y * inv + b4.y, 0.01f);
    float vz = lrelu(acc.z * inv + b4.z, 0.01f);
    float vw = lrelu(acc.w * inv + b4.w, 0.01f);

    if (POOL) {
        int g = batch[node];
        red_add_v4(&g_pool[g * H + lane * 4], vx, vy, vz, vw);
        if (lane == 0) red_add_f32(&g_cnt[g], 1.0f);
    } else {
        *(float4*)&g_h[node * H + lane * 4] = make_float4(vx, vy, vz, vw);
    }
}

// head
__global__ void k_head(const float* __restrict__ W1, const float* __restrict__ b1,
                       const float* __restrict__ W2, const float* __restrict__ b2,
                       float* __restrict__ out) {
    int g = blockIdx.x;
    int t = threadIdx.x;
    __shared__ float hg[H];
    __shared__ float z[32];
    float c = fmaxf(g_cnt[g], 1.0f);
    for (int i = t; i < H; i += 32) hg[i] = g_pool[g * H + i] / c;
    __syncthreads();
    float acc = b1[t];
#pragma unroll 8
    for (int k = 0; k < H; k++) acc += hg[k] * W1[k * 32 + t];
    z[t] = lrelu(acc, 0.01f);
    __syncthreads();
    if (t < 16) {
        float o = b2[t];
#pragma unroll
        for (int k = 0; k < 32; k++) o += z[k] * W2[k * 16 + t];
        out[g * 16 + t] = o;
    }
}

// ---------------- launch ----------------
extern "C" void kernel_launch(void* const* d_in, const int* in_sizes, int n_in,
                              void* d_out, int out_size) {
    const float* x      = (const float*)d_in[0];
    const int*   ei     = (const int*)d_in[1];
    const int*   batch  = (const int*)d_in[2];
    const float* W_nfc  = (const float*)d_in[3];
    const float* b_nfc  = (const float*)d_in[4];
    const float* Wl1    = (const float*)d_in[5];
    const float* bl1    = (const float*)d_in[6];
    const float* Wr1    = (const float*)d_in[7];
    const float* br1    = (const float*)d_in[8];
    const float* att1   = (const float*)d_in[9];
    const float* bias1  = (const float*)d_in[10];
    const float* Wl2    = (const float*)d_in[11];
    const float* bl2    = (const float*)d_in[12];
    const float* Wr2    = (const float*)d_in[13];
    const float* br2    = (const float*)d_in[14];
    const float* att2   = (const float*)d_in[15];
    const float* bias2  = (const float*)d_in[16];
    const float* W_fc1  = (const float*)d_in[17];
    const float* b_fc1  = (const float*)d_in[18];
    const float* W_fc2  = (const float*)d_in[19];
    const float* b_fc2  = (const float*)d_in[20];
    float*       out    = (float*)d_out;

    float* gh  = nullptr; cudaGetSymbolAddress((void**)&gh,  g_h);
    float* gxl = nullptr; cudaGetSymbolAddress((void**)&gxl, g_xl);
    float* gxr = nullptr; cudaGetSymbolAddress((void**)&gxr, g_xr);

    static cudaStream_t s2 = nullptr;
    static cudaEvent_t  evF = nullptr, evJ = nullptr;
    if (s2 == nullptr) {
        cudaStreamCreateWithFlags(&s2, cudaStreamNonBlocking);
        cudaEventCreateWithFlags(&evF, cudaEventDisableTiming);
        cudaEventCreateWithFlags(&evJ, cudaEventDisableTiming);
    }

    const int MB  = (NN + 127) / 128;             // 782
    const int ETB = (ET + 255) / 256;
    const int NWB = (NN * 32 + 255) / 256;

    // fork for CSR on s2; issue order chosen so the layer-1 GEMM is the
    // 4th-issued launch (that's the one ncu -s/-c captures).
    cudaEventRecord(evF, 0);
    cudaStreamWaitEvent(s2, evF, 0);

    k_init<<<NB, 256, 0, s2>>>();                                          // launch 1
    k_hist<<<ETB, 256, 0, s2>>>(ei);                                       // launch 2

    k_gemm_mma<DIN, true><<<dim3(MB, 1), 256>>>(x, W_nfc, b_nfc, gh,
                                                W_nfc, b_nfc, gh, NN);     // launch 3
    k_gemm_mma<H, false><<<dim3(MB, 2), 256>>>(gh, Wl1, bl1, gxl,
                                               Wr1, br1, gxr, NN);         // launch 4 (profiled)

    k_scan1<<<NB, 256, 0, s2>>>();                                         // launch 5
    k_scan2<<<1, 512, 0, s2>>>();
    k_scan3<<<NB, 256, 0, s2>>>();
    k_scatter<<<ETB, 256, 0, s2>>>(ei);
    cudaEventRecord(evJ, s2);

    // join CSR before first k_node
    cudaStreamWaitEvent(0, evJ, 0);

    k_node<false><<<NWB, 256>>>(att1, bias1, batch);

    k_gemm_mma<H, false><<<dim3(MB, 2), 256>>>(gh, Wl2, bl2, gxl, Wr2, br2, gxr, NN);
    k_node<true><<<NWB, 256>>>(att2, bias2, batch);

    k_head<<<NG, 32>>>(W_fc1, b_fc1, W_fc2, b_fc2, out);
}

// round 14
// speedup vs baseline: 1.1615x; 1.1141x over previous
#include <cuda_runtime.h>
#include <cuda_bf16.h>

#define NN 100000
#define NE 600000
#define ET (NE + NN)   // edges + self loops
#define H  128
#define NG 128
#define DIN 64
#define NB 391         // ceil(NN/256) scan blocks

// ---------------- scratch ----------------
__device__ float g_h[NN * H];
__device__ float g_xl[NN * H];
__device__ float g_xr[NN * H];
__device__ float g_pool[NG * H];
__device__ float g_cnt[NG];
__device__ int   g_deg[NN];
__device__ int   g_off[NN];
__device__ int   g_cursor[NN];
__device__ int   g_csrc[ET];
__device__ int   g_bsum[512];

// ---------------- helpers ----------------
__device__ __forceinline__ float lrelu(float v, float s) { return v > 0.f ? v : s * v; }

__device__ __forceinline__ void red_add_v4(float* p, float a, float b, float c, float d) {
    asm volatile("red.global.add.v4.f32 [%0], {%1,%2,%3,%4};"
                 :: "l"(p), "f"(a), "f"(b), "f"(c), "f"(d) : "memory");
}
__device__ __forceinline__ void red_add_f32(float* p, float a) {
    asm volatile("red.global.add.f32 [%0], %1;" :: "l"(p), "f"(a) : "memory");
}

// split two fp32 into packed bf16x2 hi + packed bf16x2 lo (k-pairs: v0 = even k)
__device__ __forceinline__ void bf16_split2(float v0, float v1, unsigned& hi, unsigned& lo) {
    __nv_bfloat16 h0 = __float2bfloat16(v0);
    __nv_bfloat16 h1 = __float2bfloat16(v1);
    __nv_bfloat16 l0 = __float2bfloat16(v0 - __bfloat162float(h0));
    __nv_bfloat16 l1 = __float2bfloat16(v1 - __bfloat162float(h1));
    __nv_bfloat162 hp = __halves2bfloat162(h0, h1);
    __nv_bfloat162 lp = __halves2bfloat162(l0, l1);
    hi = *reinterpret_cast<unsigned*>(&hp);
    lo = *reinterpret_cast<unsigned*>(&lp);
}
__device__ __forceinline__ void mma_bf16(float c[4],
        unsigned a0, unsigned a1, unsigned a2, unsigned a3,
        unsigned b0, unsigned b1) {
    asm volatile("mma.sync.aligned.m16n8k16.row.col.f32.bf16.bf16.f32 "
        "{%0,%1,%2,%3}, {%4,%5,%6,%7}, {%8,%9}, {%0,%1,%2,%3};"
        : "+f"(c[0]), "+f"(c[1]), "+f"(c[2]), "+f"(c[3])
        : "r"(a0), "r"(a1), "r"(a2), "r"(a3), "r"(b0), "r"(b1));
}

// ---------------- CSR build ----------------
__global__ void k_init() {
    int i = blockIdx.x * blockDim.x + threadIdx.x;
    if (i < NN) g_deg[i] = 0;
    if (i < NG * H) g_pool[i] = 0.f;
    if (i < NG) g_cnt[i] = 0.f;
}
__global__ void k_hist(const int* __restrict__ ei) {
    int e = blockIdx.x * blockDim.x + threadIdx.x;
    if (e >= ET) return;
    int d = (e < NE) ? ei[NE + e] : (e - NE);
    atomicAdd(&g_deg[d], 1);
}
__global__ void k_scan1() {
    __shared__ int sm[256];
    int t = threadIdx.x;
    int i = blockIdx.x * 256 + t;
    int v = (i < NN) ? g_deg[i] : 0;
    sm[t] = v;
    __syncthreads();
    for (int o = 1; o < 256; o <<= 1) {
        int add = (t >= o) ? sm[t - o] : 0;
        __syncthreads();
        sm[t] += add;
        __syncthreads();
    }
    if (i < NN) g_off[i] = sm[t] - v;
    if (t == 255) g_bsum[blockIdx.x] = sm[255];
}
__global__ void k_scan2() {
    __shared__ int sm[512];
    int t = threadIdx.x;
    int v = (t < NB) ? g_bsum[t] : 0;
    sm[t] = v;
    __syncthreads();
    for (int o = 1; o < 512; o <<= 1) {
        int add = (t >= o) ? sm[t - o] : 0;
        __syncthreads();
        sm[t] += add;
        __syncthreads();
    }
    if (t < NB) g_bsum[t] = sm[t] - v;
}
__global__ void k_scan3() {
    int i = blockIdx.x * 256 + threadIdx.x;
    if (i >= NN) return;
    int o = g_off[i] + g_bsum[blockIdx.x];
    g_off[i] = o;
    g_cursor[i] = o;
}
__global__ void k_scatter(const int* __restrict__ ei) {
    int e = blockIdx.x * blockDim.x + threadIdx.x;
    if (e >= ET) return;
    int s, d;
    if (e < NE) { s = ei[e]; d = ei[NE + e]; }
    else        { s = e - NE; d = s; }
    int pos = atomicAdd(&g_cursor[d], 1);
    g_csrc[pos] = s;
}

// ---------------- BF16 tensor-core GEMM (3xBF16 m16n8k16, staged hi/lo packs) ----------------
// C = lrelu?(A[M,K] @ W[K,128] + bias); 256 thr = 8 warps, CTA 128x128, warp 32x64.
// K-chunk 32 (= 16 k-pairs). smem holds packed bf16x2 hi/lo — same bytes as fp32.
#define APR 20    // As pair-row stride (uint32): g*20+th hits 32 distinct banks
#define WPR 136   // Ws pair-row stride

template<int K, bool DO_LRELU>
__global__ __launch_bounds__(256, 2) void k_gemm_mma(
    const float* __restrict__ A,
    const float* __restrict__ B0, const float* __restrict__ bias0, float* __restrict__ C0,
    const float* __restrict__ B1, const float* __restrict__ bias1, float* __restrict__ C1,
    int M)
{
    const float* Bw   = blockIdx.y ? B1 : B0;
    const float* bias = blockIdx.y ? bias1 : bias0;
    float*       C    = blockIdx.y ? C1 : C0;

    __shared__ unsigned As_h[128][APR], As_l[128][APR];   // 20480 B
    __shared__ unsigned Ws_h[16][WPR],  Ws_l[16][WPR];    // 17408 B  (total 37888 B)

    int tid  = threadIdx.x;
    int wid  = tid >> 5;
    int lane = tid & 31;
    int wr = wid & 3;            // m offset = 32*wr
    int wc = wid >> 2;           // n offset = 64*wc
    int row0 = blockIdx.x * 128;
    int g  = lane >> 2;          // groupID
    int th = lane & 3;           // thread-in-group

    const float4 z4 = make_float4(0.f, 0.f, 0.f, 0.f);
    float acc[2][8][4] = {};

    // staging coords
    int a_r = tid >> 1;                  // 0..127 (A rows; 2 threads/row)
    int a_c = (tid & 1) * 16;            // k offset 0 or 16 (handles 4 float4 = 16 k)
    int w_p = tid >> 5;                  // W pair rows: wid 0..7, +8 second half
    int w_c = (lane) * 4;                // cols 0..124

    for (int k0 = 0; k0 < K; k0 += 32) {
        // stage A: each thread converts 16 consecutive k of one row (4 float4)
#pragma unroll
        for (int q = 0; q < 4; q++) {
            int c = a_c + q * 4;
            int grow = row0 + a_r;
            float4 v = (grow < M) ? *(const float4*)&A[(long)grow * K + k0 + c] : z4;
            int p = c >> 1;              // pair index
            bf16_split2(v.x, v.y, As_h[a_r][p],     As_l[a_r][p]);
            bf16_split2(v.z, v.w, As_h[a_r][p + 1], As_l[a_r][p + 1]);
        }
        // stage W: pack across k-row pairs; each thread handles 2 pair-rows x 4 cols
#pragma unroll
        for (int q = 0; q < 2; q++) {
            int p = w_p + q * 8;         // pair 0..15
            float4 r0 = *(const float4*)&Bw[(long)(k0 + 2 * p    ) * 128 + w_c];
            float4 r1 = *(const float4*)&Bw[(long)(k0 + 2 * p + 1) * 128 + w_c];
            bf16_split2(r0.x, r1.x, Ws_h[p][w_c + 0], Ws_l[p][w_c + 0]);
            bf16_split2(r0.y, r1.y, Ws_h[p][w_c + 1], Ws_l[p][w_c + 1]);
            bf16_split2(r0.z, r1.z, Ws_h[p][w_c + 2], Ws_l[p][w_c + 2]);
            bf16_split2(r0.w, r1.w, Ws_h[p][w_c + 3], Ws_l[p][w_c + 3]);
        }
        __syncthreads();

        // mainloop: 2 x k16 steps, pure LDS + MMA
#pragma unroll
        for (int pb = 0; pb < 16; pb += 8) {   // pair base: k16 per step
            unsigned ah[2][4], al[2][4];
#pragma unroll
            for (int mt = 0; mt < 2; mt++) {
                int mb = wr * 32 + mt * 16;
                ah[mt][0] = As_h[mb + g    ][pb + th    ];
                ah[mt][1] = As_h[mb + g + 8][pb + th    ];
                ah[mt][2] = As_h[mb + g    ][pb + th + 4];
                ah[mt][3] = As_h[mb + g + 8][pb + th + 4];
                al[mt][0] = As_l[mb + g    ][pb + th    ];
                al[mt][1] = As_l[mb + g + 8][pb + th    ];
                al[mt][2] = As_l[mb + g    ][pb + th + 4];
                al[mt][3] = As_l[mb + g + 8][pb + th + 4];
            }
#pragma unroll
            for (int nt = 0; nt < 8; nt++) {
                int nb = wc * 64 + nt * 8;
                unsigned bh0 = Ws_h[pb + th    ][nb + g];
                unsigned bh1 = Ws_h[pb + th + 4][nb + g];
                unsigned bl0 = Ws_l[pb + th    ][nb + g];
                unsigned bl1 = Ws_l[pb + th + 4][nb + g];
#pragma unroll
                for (int mt = 0; mt < 2; mt++) {
                    mma_bf16(acc[mt][nt], ah[mt][0], ah[mt][1], ah[mt][2], ah[mt][3], bh0, bh1);
                    mma_bf16(acc[mt][nt], al[mt][0], al[mt][1], al[mt][2], al[mt][3], bh0, bh1);
                    mma_bf16(acc[mt][nt], ah[mt][0], ah[mt][1], ah[mt][2], ah[mt][3], bl0, bl1);
                }
            }
        }
        __syncthreads();
    }

    // epilogue: bias + optional lrelu, float2 stores
#pragma unroll
    for (int nt = 0; nt < 8; nt++) {
        int col = wc * 64 + nt * 8 + 2 * th;
        float bx = bias[col], by = bias[col + 1];
#pragma unroll
        for (int mt = 0; mt < 2; mt++) {
            int r0 = row0 + wr * 32 + mt * 16 + g;
            float* c = acc[mt][nt];
            if (r0 < M) {
                float vx = c[0] + bx, vy = c[1] + by;
                if (DO_LRELU) { vx = lrelu(vx, 0.01f); vy = lrelu(vy, 0.01f); }
                *(float2*)&C[(long)r0 * 128 + col] = make_float2(vx, vy);
            }
            if (r0 + 8 < M) {
                float vx = c[2] + bx, vy = c[3] + by;
                if (DO_LRELU) { vx = lrelu(vx, 0.01f); vy = lrelu(vy, 0.01f); }
                *(float2*)&C[(long)(r0 + 8) * 128 + col] = make_float2(vx, vy);
            }
        }
    }
}

// ---------------- fused per-node edge kernel (CSR, no atomics) ----------------
template<bool POOL>
__global__ void k_node(const float* __restrict__ att, const float* __restrict__ bias,
                       const int* __restrict__ batch) {
    int node = (blockIdx.x * blockDim.x + threadIdx.x) >> 5;
    int lane = threadIdx.x & 31;
    if (node >= NN) return;

    int start = g_off[node];
    int deg   = g_deg[node];

    float4 xr4 = *(const float4*)&g_xr[node * H + lane * 4];
    float4 t4  = *(const float4*)&att[lane * 4];

    float4 acc = make_float4(0.f, 0.f, 0.f, 0.f);
    float denom = 0.f;

    for (int base = 0; base < deg; base += 32) {
        int m = min(32, deg - base);
        int s_l = (lane < m) ? g_csrc[start + base + lane] : 0;
#pragma unroll 4
        for (int j = 0; j < m; j++) {
            int s = __shfl_sync(0xffffffffu, s_l, j);
            float4 xl4 = *(const float4*)&g_xl[s * H + lane * 4];
            float e = t4.x * lrelu(xl4.x + xr4.x, 0.2f)
                    + t4.y * lrelu(xl4.y + xr4.y, 0.2f)
                    + t4.z * lrelu(xl4.z + xr4.z, 0.2f)
                    + t4.w * lrelu(xl4.w + xr4.w, 0.2f);
#pragma unroll
            for (int o = 16; o > 0; o >>= 1) e += __shfl_xor_sync(0xffffffffu, e, o);
            float a = __expf(e);
            denom += a;
            acc.x += a * xl4.x; acc.y += a * xl4.y;
            acc.z += a * xl4.z; acc.w += a * xl4.w;
        }
    }

    float inv = 1.0f / denom;        // self-loop guarantees denom > 0
    float4 b4 = *(const float4*)&bias[lane * 4];
    float vx = lrelu(acc.x * inv + b4.x, 0.01f);
    float vy = lrelu(acc.y * inv + b4.y, 0.01f);
    float vz = lrelu(acc.z * inv + b4.z, 0.01f);
    float vw = lrelu(acc.w * inv + b4.w, 0.01f);

    if (POOL) {
        int g = batch[node];
        red_add_v4(&g_pool[g * H + lane * 4], vx, vy, vz, vw);
        if (lane == 0) red_add_f32(&g_cnt[g], 1.0f);
    } else {
        *(float4*)&g_h[node * H + lane * 4] = make_float4(vx, vy, vz, vw);
    }
}

// head
__global__ void k_head(const float* __restrict__ W1, const float* __restrict__ b1,
                       const float* __restrict__ W2, const float* __restrict__ b2,
                       float* __restrict__ out) {
    int g = blockIdx.x;
    int t = threadIdx.x;
    __shared__ float hg[H];
    __shared__ float z[32];
    float c = fmaxf(g_cnt[g], 1.0f);
    for (int i = t; i < H; i += 32) hg[i] = g_pool[g * H + i] / c;
    __syncthreads();
    float acc = b1[t];
#pragma unroll 8
    for (int k = 0; k < H; k++) acc += hg[k] * W1[k * 32 + t];
    z[t] = lrelu(acc, 0.01f);
    __syncthreads();
    if (t < 16) {
        float o = b2[t];
#pragma unroll
        for (int k = 0; k < 32; k++) o += z[k] * W2[k * 16 + t];
        out[g * 16 + t] = o;
    }
}

// ---------------- launch ----------------
extern "C" void kernel_launch(void* const* d_in, const int* in_sizes, int n_in,
                              void* d_out, int out_size) {
    const float* x      = (const float*)d_in[0];
    const int*   ei     = (const int*)d_in[1];
    const int*   batch  = (const int*)d_in[2];
    const float* W_nfc  = (const float*)d_in[3];
    const float* b_nfc  = (const float*)d_in[4];
    const float* Wl1    = (const float*)d_in[5];
    const float* bl1    = (const float*)d_in[6];
    const float* Wr1    = (const float*)d_in[7];
    const float* br1    = (const float*)d_in[8];
    const float* att1   = (const float*)d_in[9];
    const float* bias1  = (const float*)d_in[10];
    const float* Wl2    = (const float*)d_in[11];
    const float* bl2    = (const float*)d_in[12];
    const float* Wr2    = (const float*)d_in[13];
    const float* br2    = (const float*)d_in[14];
    const float* att2   = (const float*)d_in[15];
    const float* bias2  = (const float*)d_in[16];
    const float* W_fc1  = (const float*)d_in[17];
    const float* b_fc1  = (const float*)d_in[18];
    const float* W_fc2  = (const float*)d_in[19];
    const float* b_fc2  = (const float*)d_in[20];
    float*       out    = (float*)d_out;

    float* gh  = nullptr; cudaGetSymbolAddress((void**)&gh,  g_h);
    float* gxl = nullptr; cudaGetSymbolAddress((void**)&gxl, g_xl);
    float* gxr = nullptr; cudaGetSymbolAddress((void**)&gxr, g_xr);

    static cudaStream_t s2 = nullptr;
    static cudaEvent_t  evF = nullptr, evJ = nullptr;
    if (s2 == nullptr) {
        cudaStreamCreateWithFlags(&s2, cudaStreamNonBlocking);
        cudaEventCreateWithFlags(&evF, cudaEventDisableTiming);
        cudaEventCreateWithFlags(&evJ, cudaEventDisableTiming);
    }

    const int MB  = (NN + 127) / 128;             // 782
    const int ETB = (ET + 255) / 256;
    const int NWB = (NN * 32 + 255) / 256;

    // fork for CSR on s2; layer-1 GEMM kept as 4th-issued launch (ncu target)
    cudaEventRecord(evF, 0);
    cudaStreamWaitEvent(s2, evF, 0);

    k_init<<<NB, 256, 0, s2>>>();                                          // 1
    k_hist<<<ETB, 256, 0, s2>>>(ei);                                       // 2

    k_gemm_mma<DIN, true><<<dim3(MB, 1), 256>>>(x, W_nfc, b_nfc, gh,
                                                W_nfc, b_nfc, gh, NN);     // 3
    k_gemm_mma<H, false><<<dim3(MB, 2), 256>>>(gh, Wl1, bl1, gxl,
                                               Wr1, br1, gxr, NN);         // 4 (profiled)

    k_scan1<<<NB, 256, 0, s2>>>();
    k_scan2<<<1, 512, 0, s2>>>();
    k_scan3<<<NB, 256, 0, s2>>>();
    k_scatter<<<ETB, 256, 0, s2>>>(ei);
    cudaEventRecord(evJ, s2);

    cudaStreamWaitEvent(0, evJ, 0);

    k_node<false><<<NWB, 256>>>(att1, bias1, batch);

    k_gemm_mma<H, false><<<dim3(MB, 2), 256>>>(gh, Wl2, bl2, gxl, Wr2, br2, gxr, NN);
    k_node<true><<<NWB, 256>>>(att2, bias2, batch);

    k_head<<<NG, 32>>>(W_fc1, b_fc1, W_fc2, b_fc2, out);
}

// round 15
// speedup vs baseline: 1.2407x; 1.0682x over previous
#include <cuda_runtime.h>
#include <cuda_bf16.h>

#define NN 100000
#define NE 600000
#define ET (NE + NN)   // edges + self loops
#define H  128
#define NG 128
#define DIN 64
#define NB 391         // ceil(NN/256) scan blocks

// ---------------- scratch ----------------
__device__ float g_h[NN * H];
__device__ float g_xl[NN * H];
__device__ float g_xr[NN * H];
__device__ float g_pool[NG * H];
__device__ float g_cnt[NG];
__device__ int   g_deg[NN];
__device__ int   g_off[NN];
__device__ int   g_cursor[NN];
__device__ int   g_csrc[ET];
__device__ int   g_bsum[512];

// ---------------- helpers ----------------
__device__ __forceinline__ float lrelu(float v, float s) { return v > 0.f ? v : s * v; }

__device__ __forceinline__ void red_add_v4(float* p, float a, float b, float c, float d) {
    asm volatile("red.global.add.v4.f32 [%0], {%1,%2,%3,%4};"
                 :: "l"(p), "f"(a), "f"(b), "f"(c), "f"(d) : "memory");
}
__device__ __forceinline__ void red_add_f32(float* p, float a) {
    asm volatile("red.global.add.f32 [%0], %1;" :: "l"(p), "f"(a) : "memory");
}

// split two fp32 into packed bf16x2 hi + packed bf16x2 lo (v0 = even k)
__device__ __forceinline__ void bf16_split2(float v0, float v1, unsigned& hi, unsigned& lo) {
    __nv_bfloat16 h0 = __float2bfloat16(v0);
    __nv_bfloat16 h1 = __float2bfloat16(v1);
    __nv_bfloat16 l0 = __float2bfloat16(v0 - __bfloat162float(h0));
    __nv_bfloat16 l1 = __float2bfloat16(v1 - __bfloat162float(h1));
    __nv_bfloat162 hp = __halves2bfloat162(h0, h1);
    __nv_bfloat162 lp = __halves2bfloat162(l0, l1);
    hi = *reinterpret_cast<unsigned*>(&hp);
    lo = *reinterpret_cast<unsigned*>(&lp);
}
__device__ __forceinline__ void mma_bf16(float c[4],
        unsigned a0, unsigned a1, unsigned a2, unsigned a3,
        unsigned b0, unsigned b1) {
    asm volatile("mma.sync.aligned.m16n8k16.row.col.f32.bf16.bf16.f32 "
        "{%0,%1,%2,%3}, {%4,%5,%6,%7}, {%8,%9}, {%0,%1,%2,%3};"
        : "+f"(c[0]), "+f"(c[1]), "+f"(c[2]), "+f"(c[3])
        : "r"(a0), "r"(a1), "r"(a2), "r"(a3), "r"(b0), "r"(b1));
}
__device__ __forceinline__ void ldsm_x4(unsigned r[4], unsigned saddr) {
    asm volatile("ldmatrix.sync.aligned.m8n8.x4.shared.b16 {%0,%1,%2,%3}, [%4];"
                 : "=r"(r[0]), "=r"(r[1]), "=r"(r[2]), "=r"(r[3]) : "r"(saddr));
}

// ---------------- CSR build ----------------
__global__ void k_init() {
    int i = blockIdx.x * blockDim.x + threadIdx.x;
    if (i < NN) g_deg[i] = 0;
    if (i < NG * H) g_pool[i] = 0.f;
    if (i < NG) g_cnt[i] = 0.f;
}
__global__ void k_hist(const int* __restrict__ ei) {
    int e = blockIdx.x * blockDim.x + threadIdx.x;
    if (e >= ET) return;
    int d = (e < NE) ? ei[NE + e] : (e - NE);
    atomicAdd(&g_deg[d], 1);
}
__global__ void k_scan1() {
    __shared__ int sm[256];
    int t = threadIdx.x;
    int i = blockIdx.x * 256 + t;
    int v = (i < NN) ? g_deg[i] : 0;
    sm[t] = v;
    __syncthreads();
    for (int o = 1; o < 256; o <<= 1) {
        int add = (t >= o) ? sm[t - o] : 0;
        __syncthreads();
        sm[t] += add;
        __syncthreads();
    }
    if (i < NN) g_off[i] = sm[t] - v;
    if (t == 255) g_bsum[blockIdx.x] = sm[255];
}
__global__ void k_scan2() {
    __shared__ int sm[512];
    int t = threadIdx.x;
    int v = (t < NB) ? g_bsum[t] : 0;
    sm[t] = v;
    __syncthreads();
    for (int o = 1; o < 512; o <<= 1) {
        int add = (t >= o) ? sm[t - o] : 0;
        __syncthreads();
        sm[t] += add;
        __syncthreads();
    }
    if (t < NB) g_bsum[t] = sm[t] - v;
}
__global__ void k_scan3() {
    int i = blockIdx.x * 256 + threadIdx.x;
    if (i >= NN) return;
    int o = g_off[i] + g_bsum[blockIdx.x];
    g_off[i] = o;
    g_cursor[i] = o;
}
__global__ void k_scatter(const int* __restrict__ ei) {
    int e = blockIdx.x * blockDim.x + threadIdx.x;
    if (e >= ET) return;
    int s, d;
    if (e < NE) { s = ei[e]; d = ei[NE + e]; }
    else        { s = e - NE; d = s; }
    int pos = atomicAdd(&g_cursor[d], 1);
    g_csrc[pos] = s;
}

// ---------------- BF16 tensor-core GEMM (3xBF16 m16n8k16 + ldmatrix) ----------------
// C = lrelu?(A[M,K] @ W[K,128] + bias); 256 thr = 8 warps, CTA 128x128, warp 32x64.
// A staged [row][pair] (stride 20), W staged COLUMN-major [col][pair] (stride 20)
// so all fragments load via ldmatrix.x4.
#define APR 20
#define WPR2 20

template<int K, bool DO_LRELU>
__global__ __launch_bounds__(256, 2) void k_gemm_mma(
    const float* __restrict__ A,
    const float* __restrict__ B0, const float* __restrict__ bias0, float* __restrict__ C0,
    const float* __restrict__ B1, const float* __restrict__ bias1, float* __restrict__ C1,
    int M)
{
    const float* Bw   = blockIdx.y ? B1 : B0;
    const float* bias = blockIdx.y ? bias1 : bias0;
    float*       C    = blockIdx.y ? C1 : C0;

    __shared__ unsigned As_h[128][APR],  As_l[128][APR];    // 20480 B
    __shared__ unsigned Ws_h[128][WPR2], Ws_l[128][WPR2];   // 20480 B  (40960 total)

    int tid  = threadIdx.x;
    int wid  = tid >> 5;
    int lane = tid & 31;
    int wr = wid & 3;            // m offset = 32*wr
    int wc = wid >> 2;           // n offset = 64*wc
    int row0 = blockIdx.x * 128;
    int g  = lane >> 2;
    int th = lane & 3;

    const float4 z4 = make_float4(0.f, 0.f, 0.f, 0.f);
    float acc[2][8][4] = {};

    // staging coords
    int a_r = tid >> 1;                  // A row (2 threads/row)
    int a_c = (tid & 1) * 16;            // k offset 0 or 16
    int w_col = tid & 127;               // W column
    int w_pg  = (tid >> 7) * 8;          // pair group 0 or 8

    // ldmatrix lane->address precompute (pair offsets added per step)
    int a_row_l = wr * 32 + (lane & 15);           // + mt*16
    int a_po    = (lane >> 4) << 2;                // 0 or 4
    unsigned a_h0 = (unsigned)__cvta_generic_to_shared(&As_h[a_row_l][a_po]);
    unsigned a_l0 = (unsigned)__cvta_generic_to_shared(&As_l[a_row_l][a_po]);
    int b_col_l = wc * 64 + (lane & 7) + ((lane >> 4) << 3);   // + ntp*16
    int b_po    = ((lane >> 3) & 1) << 2;                      // 0 or 4
    unsigned b_h0 = (unsigned)__cvta_generic_to_shared(&Ws_h[b_col_l][b_po]);
    unsigned b_l0 = (unsigned)__cvta_generic_to_shared(&Ws_l[b_col_l][b_po]);

    for (int k0 = 0; k0 < K; k0 += 32) {
        // stage A: thread converts 16 consecutive k of one row
#pragma unroll
        for (int q = 0; q < 4; q++) {
            int c = a_c + q * 4;
            int grow = row0 + a_r;
            float4 v = (grow < M) ? *(const float4*)&A[(long)grow * K + k0 + c] : z4;
            int p = c >> 1;
            bf16_split2(v.x, v.y, As_h[a_r][p],     As_l[a_r][p]);
            bf16_split2(v.z, v.w, As_h[a_r][p + 1], As_l[a_r][p + 1]);
        }
        // stage W column-major: thread owns (col, 8 pairs); loads coalesced by row
#pragma unroll
        for (int q = 0; q < 8; q++) {
            int p = w_pg + q;
            float v0 = Bw[(long)(k0 + 2 * p    ) * 128 + w_col];
            float v1 = Bw[(long)(k0 + 2 * p + 1) * 128 + w_col];
            bf16_split2(v0, v1, Ws_h[w_col][p], Ws_l[w_col][p]);
        }
        __syncthreads();

        // mainloop: 2 x k16 steps, ldmatrix + MMA only
#pragma unroll
        for (int pb = 0; pb < 16; pb += 8) {
            unsigned ah[2][4], al[2][4];
#pragma unroll
            for (int mt = 0; mt < 2; mt++) {
                unsigned off = (mt * 16 * APR + pb) * 4;     // bytes
                ldsm_x4(ah[mt], a_h0 + off);
                ldsm_x4(al[mt], a_l0 + off);
            }
#pragma unroll
            for (int ntp = 0; ntp < 4; ntp++) {              // 2 n-tiles per ldmatrix
                unsigned off = (ntp * 16 * WPR2 + pb) * 4;
                unsigned bh[4], bl[4];
                ldsm_x4(bh, b_h0 + off);
                ldsm_x4(bl, b_l0 + off);
#pragma unroll
                for (int hf = 0; hf < 2; hf++) {
                    int nt = ntp * 2 + hf;
                    unsigned b0h = bh[hf * 2], b1h = bh[hf * 2 + 1];
                    unsigned b0l = bl[hf * 2], b1l = bl[hf * 2 + 1];
#pragma unroll
                    for (int mt = 0; mt < 2; mt++) {
                        mma_bf16(acc[mt][nt], ah[mt][0], ah[mt][1], ah[mt][2], ah[mt][3], b0h, b1h);
                        mma_bf16(acc[mt][nt], al[mt][0], al[mt][1], al[mt][2], al[mt][3], b0h, b1h);
                        mma_bf16(acc[mt][nt], ah[mt][0], ah[mt][1], ah[mt][2], ah[mt][3], b0l, b1l);
                    }
                }
            }
        }
        __syncthreads();
    }

    // epilogue: bias + optional lrelu, float2 stores
#pragma unroll
    for (int nt = 0; nt < 8; nt++) {
        int col = wc * 64 + nt * 8 + 2 * th;
        float bx = bias[col], by = bias[col + 1];
#pragma unroll
        for (int mt = 0; mt < 2; mt++) {
            int r0 = row0 + wr * 32 + mt * 16 + g;
            float* c = acc[mt][nt];
            if (r0 < M) {
                float vx = c[0] + bx, vy = c[1] + by;
                if (DO_LRELU) { vx = lrelu(vx, 0.01f); vy = lrelu(vy, 0.01f); }
                *(float2*)&C[(long)r0 * 128 + col] = make_float2(vx, vy);
            }
            if (r0 + 8 < M) {
                float vx = c[2] + bx, vy = c[3] + by;
                if (DO_LRELU) { vx = lrelu(vx, 0.01f); vy = lrelu(vy, 0.01f); }
                *(float2*)&C[(long)(r0 + 8) * 128 + col] = make_float2(vx, vy);
            }
        }
    }
}

// ---------------- fused per-node edge kernel (CSR, no atomics) ----------------
template<bool POOL>
__global__ void k_node(const float* __restrict__ att, const float* __restrict__ bias,
                       const int* __restrict__ batch) {
    int node = (blockIdx.x * blockDim.x + threadIdx.x) >> 5;
    int lane = threadIdx.x & 31;
    if (node >= NN) return;

    int start = g_off[node];
    int deg   = g_deg[node];

    float4 xr4 = *(const float4*)&g_xr[node * H + lane * 4];
    float4 t4  = *(const float4*)&att[lane * 4];

    float4 acc = make_float4(0.f, 0.f, 0.f, 0.f);
    float denom = 0.f;

    for (int base = 0; base < deg; base += 32) {
        int m = min(32, deg - base);
        int s_l = (lane < m) ? g_csrc[start + base + lane] : 0;
#pragma unroll 4
        for (int j = 0; j < m; j++) {
            int s = __shfl_sync(0xffffffffu, s_l, j);
            float4 xl4 = *(const float4*)&g_xl[s * H + lane * 4];
            float e = t4.x * lrelu(xl4.x + xr4.x, 0.2f)
                    + t4.y * lrelu(xl4.y + xr4.y, 0.2f)
                    + t4.z * lrelu(xl4.z + xr4.z, 0.2f)
                    + t4.w * lrelu(xl4.w + xr4.w, 0.2f);
#pragma unroll
            for (int o = 16; o > 0; o >>= 1) e += __shfl_xor_sync(0xffffffffu, e, o);
            float a = __expf(e);
            denom += a;
            acc.x += a * xl4.x; acc.y += a * xl4.y;
            acc.z += a * xl4.z; acc.w += a * xl4.w;
        }
    }

    float inv = 1.0f / denom;        // self-loop guarantees denom > 0
    float4 b4 = *(const float4*)&bias[lane * 4];
    float vx = lrelu(acc.x * inv + b4.x, 0.01f);
    float vy = lrelu(acc.y * inv + b4.y, 0.01f);
    float vz = lrelu(acc.z * inv + b4.z, 0.01f);
    float vw = lrelu(acc.w * inv + b4.w, 0.01f);

    if (POOL) {
        int g = batch[node];
        red_add_v4(&g_pool[g * H + lane * 4], vx, vy, vz, vw);
        if (lane == 0) red_add_f32(&g_cnt[g], 1.0f);
    } else {
        *(float4*)&g_h[node * H + lane * 4] = make_float4(vx, vy, vz, vw);
    }
}

// head
__global__ void k_head(const float* __restrict__ W1, const float* __restrict__ b1,
                       const float* __restrict__ W2, const float* __restrict__ b2,
                       float* __restrict__ out) {
    int g = blockIdx.x;
    int t = threadIdx.x;
    __shared__ float hg[H];
    __shared__ float z[32];
    float c = fmaxf(g_cnt[g], 1.0f);
    for (int i = t; i < H; i += 32) hg[i] = g_pool[g * H + i] / c;
    __syncthreads();
    float acc = b1[t];
#pragma unroll 8
    for (int k = 0; k < H; k++) acc += hg[k] * W1[k * 32 + t];
    z[t] = lrelu(acc, 0.01f);
    __syncthreads();
    if (t < 16) {
        float o = b2[t];
#pragma unroll
        for (int k = 0; k < 32; k++) o += z[k] * W2[k * 16 + t];
        out[g * 16 + t] = o;
    }
}

// ---------------- launch ----------------
extern "C" void kernel_launch(void* const* d_in, const int* in_sizes, int n_in,
                              void* d_out, int out_size) {
    const float* x      = (const float*)d_in[0];
    const int*   ei     = (const int*)d_in[1];
    const int*   batch  = (const int*)d_in[2];
    const float* W_nfc  = (const float*)d_in[3];
    const float* b_nfc  = (const float*)d_in[4];
    const float* Wl1    = (const float*)d_in[5];
    const float* bl1    = (const float*)d_in[6];
    const float* Wr1    = (const float*)d_in[7];
    const float* br1    = (const float*)d_in[8];
    const float* att1   = (const float*)d_in[9];
    const float* bias1  = (const float*)d_in[10];
    const float* Wl2    = (const float*)d_in[11];
    const float* bl2    = (const float*)d_in[12];
    const float* Wr2    = (const float*)d_in[13];
    const float* br2    = (const float*)d_in[14];
    const float* att2   = (const float*)d_in[15];
    const float* bias2  = (const float*)d_in[16];
    const float* W_fc1  = (const float*)d_in[17];
    const float* b_fc1  = (const float*)d_in[18];
    const float* W_fc2  = (const float*)d_in[19];
    const float* b_fc2  = (const float*)d_in[20];
    float*       out    = (float*)d_out;

    float* gh  = nullptr; cudaGetSymbolAddress((void**)&gh,  g_h);
    float* gxl = nullptr; cudaGetSymbolAddress((void**)&gxl, g_xl);
    float* gxr = nullptr; cudaGetSymbolAddress((void**)&gxr, g_xr);

    static cudaStream_t s2 = nullptr;
    static cudaEvent_t  evF = nullptr, evJ = nullptr;
    if (s2 == nullptr) {
        cudaStreamCreateWithFlags(&s2, cudaStreamNonBlocking);
        cudaEventCreateWithFlags(&evF, cudaEventDisableTiming);
        cudaEventCreateWithFlags(&evJ, cudaEventDisableTiming);
    }

    const int MB  = (NN + 127) / 128;             // 782
    const int ETB = (ET + 255) / 256;
    const int NWB = (NN * 32 + 255) / 256;

    // fork for CSR on s2; layer-1 GEMM kept as 4th-issued launch (ncu target)
    cudaEventRecord(evF, 0);
    cudaStreamWaitEvent(s2, evF, 0);

    k_init<<<NB, 256, 0, s2>>>();                                          // 1
    k_hist<<<ETB, 256, 0, s2>>>(ei);                                       // 2

    k_gemm_mma<DIN, true><<<dim3(MB, 1), 256>>>(x, W_nfc, b_nfc, gh,
                                                W_nfc, b_nfc, gh, NN);     // 3
    k_gemm_mma<H, false><<<dim3(MB, 2), 256>>>(gh, Wl1, bl1, gxl,
                                               Wr1, br1, gxr, NN);         // 4 (profiled)

    k_scan1<<<NB, 256, 0, s2>>>();
    k_scan2<<<1, 512, 0, s2>>>();
    k_scan3<<<NB, 256, 0, s2>>>();
    k_scatter<<<ETB, 256, 0, s2>>>(ei);
    cudaEventRecord(evJ, s2);

    cudaStreamWaitEvent(0, evJ, 0);

    k_node<false><<<NWB, 256>>>(att1, bias1, batch);

    k_gemm_mma<H, false><<<dim3(MB, 2), 256>>>(gh, Wl2, bl2, gxl, Wr2, br2, gxr, NN);
    k_node<true><<<NWB, 256>>>(att2, bias2, batch);

    k_head<<<NG, 32>>>(W_fc1, b_fc1, W_fc2, b_fc2, out);
}

// round 16
// speedup vs baseline: 1.2609x; 1.0163x over previous
#include <cuda_runtime.h>
#include <cuda_bf16.h>

#define NN 100000
#define NE 600000
#define ET (NE + NN)   // edges + self loops
#define H  128
#define NG 128
#define DIN 64
#define NB 391         // ceil(NN/256) scan blocks

// ---------------- scratch ----------------
__device__ float g_h[NN * H];
__device__ float g_xl[NN * H];
__device__ float g_xr[NN * H];
__device__ float g_pool[NG * H];
__device__ float g_cnt[NG];
__device__ int   g_deg[NN];
__device__ int   g_off[NN];
__device__ int   g_cursor[NN];
__device__ int   g_csrc[ET];
__device__ int   g_bsum[512];

// ---------------- helpers ----------------
__device__ __forceinline__ float lrelu(float v, float s) { return v > 0.f ? v : s * v; }

__device__ __forceinline__ void red_add_v4(float* p, float a, float b, float c, float d) {
    asm volatile("red.global.add.v4.f32 [%0], {%1,%2,%3,%4};"
                 :: "l"(p), "f"(a), "f"(b), "f"(c), "f"(d) : "memory");
}
__device__ __forceinline__ void red_add_f32(float* p, float a) {
    asm volatile("red.global.add.f32 [%0], %1;" :: "l"(p), "f"(a) : "memory");
}

// split two fp32 into packed bf16x2 hi + packed bf16x2 lo (v0 = even k)
__device__ __forceinline__ void bf16_split2(float v0, float v1, unsigned& hi, unsigned& lo) {
    __nv_bfloat16 h0 = __float2bfloat16(v0);
    __nv_bfloat16 h1 = __float2bfloat16(v1);
    __nv_bfloat16 l0 = __float2bfloat16(v0 - __bfloat162float(h0));
    __nv_bfloat16 l1 = __float2bfloat16(v1 - __bfloat162float(h1));
    __nv_bfloat162 hp = __halves2bfloat162(h0, h1);
    __nv_bfloat162 lp = __halves2bfloat162(l0, l1);
    hi = *reinterpret_cast<unsigned*>(&hp);
    lo = *reinterpret_cast<unsigned*>(&lp);
}
__device__ __forceinline__ void mma_bf16(float c[4],
        unsigned a0, unsigned a1, unsigned a2, unsigned a3,
        unsigned b0, unsigned b1) {
    asm volatile("mma.sync.aligned.m16n8k16.row.col.f32.bf16.bf16.f32 "
        "{%0,%1,%2,%3}, {%4,%5,%6,%7}, {%8,%9}, {%0,%1,%2,%3};"
        : "+f"(c[0]), "+f"(c[1]), "+f"(c[2]), "+f"(c[3])
        : "r"(a0), "r"(a1), "r"(a2), "r"(a3), "r"(b0), "r"(b1));
}
__device__ __forceinline__ void ldsm_x4(unsigned r[4], unsigned saddr) {
    asm volatile("ldmatrix.sync.aligned.m8n8.x4.shared.b16 {%0,%1,%2,%3}, [%4];"
                 : "=r"(r[0]), "=r"(r[1]), "=r"(r[2]), "=r"(r[3]) : "r"(saddr));
}

// ---------------- CSR build ----------------
__global__ void k_init() {
    int i = blockIdx.x * blockDim.x + threadIdx.x;
    if (i < NN) g_deg[i] = 0;
    if (i < NG * H) g_pool[i] = 0.f;
    if (i < NG) g_cnt[i] = 0.f;
}
__global__ void k_hist(const int* __restrict__ ei) {
    int e = blockIdx.x * blockDim.x + threadIdx.x;
    if (e >= ET) return;
    int d = (e < NE) ? ei[NE + e] : (e - NE);
    atomicAdd(&g_deg[d], 1);
}
__global__ void k_scan1() {
    __shared__ int sm[256];
    int t = threadIdx.x;
    int i = blockIdx.x * 256 + t;
    int v = (i < NN) ? g_deg[i] : 0;
    sm[t] = v;
    __syncthreads();
    for (int o = 1; o < 256; o <<= 1) {
        int add = (t >= o) ? sm[t - o] : 0;
        __syncthreads();
        sm[t] += add;
        __syncthreads();
    }
    if (i < NN) g_off[i] = sm[t] - v;
    if (t == 255) g_bsum[blockIdx.x] = sm[255];
}
__global__ void k_scan2() {
    __shared__ int sm[512];
    int t = threadIdx.x;
    int v = (t < NB) ? g_bsum[t] : 0;
    sm[t] = v;
    __syncthreads();
    for (int o = 1; o < 512; o <<= 1) {
        int add = (t >= o) ? sm[t - o] : 0;
        __syncthreads();
        sm[t] += add;
        __syncthreads();
    }
    if (t < NB) g_bsum[t] = sm[t] - v;
}
__global__ void k_scan3() {
    int i = blockIdx.x * 256 + threadIdx.x;
    if (i >= NN) return;
    int o = g_off[i] + g_bsum[blockIdx.x];
    g_off[i] = o;
    g_cursor[i] = o;
}
__global__ void k_scatter(const int* __restrict__ ei) {
    int e = blockIdx.x * blockDim.x + threadIdx.x;
    if (e >= ET) return;
    int s, d;
    if (e < NE) { s = ei[e]; d = ei[NE + e]; }
    else        { s = e - NE; d = s; }
    int pos = atomicAdd(&g_cursor[d], 1);
    g_csrc[pos] = s;
}

// ---------------- BF16 tensor-core GEMM (3xBF16, ldmatrix, term-major MMA sched) ----------------
// C = lrelu?(A[M,K] @ W[K,128] + bias); 256 thr = 8 warps, CTA 128x128, warp 32x64.
// Per k16 step: load ALL fragments, then 3 passes of 16 independent MMAs
// (hi*hi, lo*hi, hi*lo) — same-acc deps spaced 16 apart.
#define APR 20
#define WPR2 20

template<int K, bool DO_LRELU>
__global__ __launch_bounds__(256, 2) void k_gemm_mma(
    const float* __restrict__ A,
    const float* __restrict__ B0, const float* __restrict__ bias0, float* __restrict__ C0,
    const float* __restrict__ B1, const float* __restrict__ bias1, float* __restrict__ C1,
    int M)
{
    const float* Bw   = blockIdx.y ? B1 : B0;
    const float* bias = blockIdx.y ? bias1 : bias0;
    float*       C    = blockIdx.y ? C1 : C0;

    __shared__ unsigned As_h[128][APR],  As_l[128][APR];    // 20480 B
    __shared__ unsigned Ws_h[128][WPR2], Ws_l[128][WPR2];   // 20480 B

    int tid  = threadIdx.x;
    int wid  = tid >> 5;
    int lane = tid & 31;
    int wr = wid & 3;            // m offset = 32*wr
    int wc = wid >> 2;           // n offset = 64*wc
    int row0 = blockIdx.x * 128;
    int g  = lane >> 2;
    int th = lane & 3;

    const float4 z4 = make_float4(0.f, 0.f, 0.f, 0.f);
    float acc[2][8][4] = {};

    // staging coords
    int a_r = tid >> 1;                  // A row (2 threads/row)
    int a_c = (tid & 1) * 16;            // k offset 0 or 16
    int w_col = tid & 127;               // W column
    int w_pg  = (tid >> 7) * 8;          // pair group 0 or 8

    // ldmatrix lane->address precompute
    int a_row_l = wr * 32 + (lane & 15);
    int a_po    = (lane >> 4) << 2;
    unsigned a_h0 = (unsigned)__cvta_generic_to_shared(&As_h[a_row_l][a_po]);
    unsigned a_l0 = (unsigned)__cvta_generic_to_shared(&As_l[a_row_l][a_po]);
    int b_col_l = wc * 64 + (lane & 7) + ((lane >> 4) << 3);
    int b_po    = ((lane >> 3) & 1) << 2;
    unsigned b_h0 = (unsigned)__cvta_generic_to_shared(&Ws_h[b_col_l][b_po]);
    unsigned b_l0 = (unsigned)__cvta_generic_to_shared(&Ws_l[b_col_l][b_po]);

    for (int k0 = 0; k0 < K; k0 += 32) {
        // stage A
#pragma unroll
        for (int q = 0; q < 4; q++) {
            int c = a_c + q * 4;
            int grow = row0 + a_r;
            float4 v = (grow < M) ? *(const float4*)&A[(long)grow * K + k0 + c] : z4;
            int p = c >> 1;
            bf16_split2(v.x, v.y, As_h[a_r][p],     As_l[a_r][p]);
            bf16_split2(v.z, v.w, As_h[a_r][p + 1], As_l[a_r][p + 1]);
        }
        // stage W column-major
#pragma unroll
        for (int q = 0; q < 8; q++) {
            int p = w_pg + q;
            float v0 = Bw[(long)(k0 + 2 * p    ) * 128 + w_col];
            float v1 = Bw[(long)(k0 + 2 * p + 1) * 128 + w_col];
            bf16_split2(v0, v1, Ws_h[w_col][p], Ws_l[w_col][p]);
        }
        __syncthreads();

#pragma unroll
        for (int pb = 0; pb < 16; pb += 8) {
            // load ALL fragments for this k16 step
            unsigned ah[2][4], al[2][4], bh[4][4], bl[4][4];
#pragma unroll
            for (int mt = 0; mt < 2; mt++) {
                unsigned off = (mt * 16 * APR + pb) * 4;
                ldsm_x4(ah[mt], a_h0 + off);
                ldsm_x4(al[mt], a_l0 + off);
            }
#pragma unroll
            for (int ntp = 0; ntp < 4; ntp++) {
                unsigned off = (ntp * 16 * WPR2 + pb) * 4;
                ldsm_x4(bh[ntp], b_h0 + off);
                ldsm_x4(bl[ntp], b_l0 + off);
            }
            // pass 1: hi*hi — 16 independent MMAs
#pragma unroll
            for (int nt = 0; nt < 8; nt++) {
                unsigned b0 = bh[nt >> 1][(nt & 1) * 2], b1 = bh[nt >> 1][(nt & 1) * 2 + 1];
#pragma unroll
                for (int mt = 0; mt < 2; mt++)
                    mma_bf16(acc[mt][nt], ah[mt][0], ah[mt][1], ah[mt][2], ah[mt][3], b0, b1);
            }
            // pass 2: lo*hi
#pragma unroll
            for (int nt = 0; nt < 8; nt++) {
                unsigned b0 = bh[nt >> 1][(nt & 1) * 2], b1 = bh[nt >> 1][(nt & 1) * 2 + 1];
#pragma unroll
                for (int mt = 0; mt < 2; mt++)
                    mma_bf16(acc[mt][nt], al[mt][0], al[mt][1], al[mt][2], al[mt][3], b0, b1);
            }
            // pass 3: hi*lo
#pragma unroll
            for (int nt = 0; nt < 8; nt++) {
                unsigned b0 = bl[nt >> 1][(nt & 1) * 2], b1 = bl[nt >> 1][(nt & 1) * 2 + 1];
#pragma unroll
                for (int mt = 0; mt < 2; mt++)
                    mma_bf16(acc[mt][nt], ah[mt][0], ah[mt][1], ah[mt][2], ah[mt][3], b0, b1);
            }
        }
        __syncthreads();
    }

    // epilogue: bias + optional lrelu, float2 stores
#pragma unroll
    for (int nt = 0; nt < 8; nt++) {
        int col = wc * 64 + nt * 8 + 2 * th;
        float bx = bias[col], by = bias[col + 1];
#pragma unroll
        for (int mt = 0; mt < 2; mt++) {
            int r0 = row0 + wr * 32 + mt * 16 + g;
            float* c = acc[mt][nt];
            if (r0 < M) {
                float vx = c[0] + bx, vy = c[1] + by;
                if (DO_LRELU) { vx = lrelu(vx, 0.01f); vy = lrelu(vy, 0.01f); }
                *(float2*)&C[(long)r0 * 128 + col] = make_float2(vx, vy);
            }
            if (r0 + 8 < M) {
                float vx = c[2] + bx, vy = c[3] + by;
                if (DO_LRELU) { vx = lrelu(vx, 0.01f); vy = lrelu(vy, 0.01f); }
                *(float2*)&C[(long)(r0 + 8) * 128 + col] = make_float2(vx, vy);
            }
        }
    }
}

// ---------------- fused per-node edge kernel (CSR, no atomics) ----------------
template<bool POOL>
__global__ void k_node(const float* __restrict__ att, const float* __restrict__ bias,
                       const int* __restrict__ batch) {
    int node = (blockIdx.x * blockDim.x + threadIdx.x) >> 5;
    int lane = threadIdx.x & 31;
    if (node >= NN) return;

    int start = g_off[node];
    int deg   = g_deg[node];

    float4 xr4 = *(const float4*)&g_xr[node * H + lane * 4];
    float4 t4  = *(const float4*)&att[lane * 4];

    float4 acc = make_float4(0.f, 0.f, 0.f, 0.f);
    float denom = 0.f;

    for (int base = 0; base < deg; base += 32) {
        int m = min(32, deg - base);
        int s_l = (lane < m) ? g_csrc[start + base + lane] : 0;
#pragma unroll 4
        for (int j = 0; j < m; j++) {
            int s = __shfl_sync(0xffffffffu, s_l, j);
            float4 xl4 = *(const float4*)&g_xl[s * H + lane * 4];
            float e = t4.x * lrelu(xl4.x + xr4.x, 0.2f)
                    + t4.y * lrelu(xl4.y + xr4.y, 0.2f)
                    + t4.z * lrelu(xl4.z + xr4.z, 0.2f)
                    + t4.w * lrelu(xl4.w + xr4.w, 0.2f);
#pragma unroll
            for (int o = 16; o > 0; o >>= 1) e += __shfl_xor_sync(0xffffffffu, e, o);
            float a = __expf(e);
            denom += a;
            acc.x += a * xl4.x; acc.y += a * xl4.y;
            acc.z += a * xl4.z; acc.w += a * xl4.w;
        }
    }

    float inv = 1.0f / denom;        // self-loop guarantees denom > 0
    float4 b4 = *(const float4*)&bias[lane * 4];
    float vx = lrelu(acc.x * inv + b4.x, 0.01f);
    float vy = lrelu(acc.y * inv + b4.y, 0.01f);
    float vz = lrelu(acc.z * inv + b4.z, 0.01f);
    float vw = lrelu(acc.w * inv + b4.w, 0.01f);

    if (POOL) {
        int g = batch[node];
        red_add_v4(&g_pool[g * H + lane * 4], vx, vy, vz, vw);
        if (lane == 0) red_add_f32(&g_cnt[g], 1.0f);
    } else {
        *(float4*)&g_h[node * H + lane * 4] = make_float4(vx, vy, vz, vw);
    }
}

// head
__global__ void k_head(const float* __restrict__ W1, const float* __restrict__ b1,
                       const float* __restrict__ W2, const float* __restrict__ b2,
                       float* __restrict__ out) {
    int g = blockIdx.x;
    int t = threadIdx.x;
    __shared__ float hg[H];
    __shared__ float z[32];
    float c = fmaxf(g_cnt[g], 1.0f);
    for (int i = t; i < H; i += 32) hg[i] = g_pool[g * H + i] / c;
    __syncthreads();
    float acc = b1[t];
#pragma unroll 8
    for (int k = 0; k < H; k++) acc += hg[k] * W1[k * 32 + t];
    z[t] = lrelu(acc, 0.01f);
    __syncthreads();
    if (t < 16) {
        float o = b2[t];
#pragma unroll
        for (int k = 0; k < 32; k++) o += z[k] * W2[k * 16 + t];
        out[g * 16 + t] = o;
    }
}

// ---------------- launch ----------------
extern "C" void kernel_launch(void* const* d_in, const int* in_sizes, int n_in,
                              void* d_out, int out_size) {
    const float* x      = (const float*)d_in[0];
    const int*   ei     = (const int*)d_in[1];
    const int*   batch  = (const int*)d_in[2];
    const float* W_nfc  = (const float*)d_in[3];
    const float* b_nfc  = (const float*)d_in[4];
    const float* Wl1    = (const float*)d_in[5];
    const float* bl1    = (const float*)d_in[6];
    const float* Wr1    = (const float*)d_in[7];
    const float* br1    = (const float*)d_in[8];
    const float* att1   = (const float*)d_in[9];
    const float* bias1  = (const float*)d_in[10];
    const float* Wl2    = (const float*)d_in[11];
    const float* bl2    = (const float*)d_in[12];
    const float* Wr2    = (const float*)d_in[13];
    const float* br2    = (const float*)d_in[14];
    const float* att2   = (const float*)d_in[15];
    const float* bias2  = (const float*)d_in[16];
    const float* W_fc1  = (const float*)d_in[17];
    const float* b_fc1  = (const float*)d_in[18];
    const float* W_fc2  = (const float*)d_in[19];
    const float* b_fc2  = (const float*)d_in[20];
    float*       out    = (float*)d_out;

    float* gh  = nullptr; cudaGetSymbolAddress((void**)&gh,  g_h);
    float* gxl = nullptr; cudaGetSymbolAddress((void**)&gxl, g_xl);
    float* gxr = nullptr; cudaGetSymbolAddress((void**)&gxr, g_xr);

    static cudaStream_t s2 = nullptr;
    static cudaEvent_t  evF = nullptr, evJ = nullptr;
    if (s2 == nullptr) {
        cudaStreamCreateWithFlags(&s2, cudaStreamNonBlocking);
        cudaEventCreateWithFlags(&evF, cudaEventDisableTiming);
        cudaEventCreateWithFlags(&evJ, cudaEventDisableTiming);
    }

    const int MB  = (NN + 127) / 128;             // 782
    const int ETB = (ET + 255) / 256;
    const int NWB = (NN * 32 + 255) / 256;

    // fork for CSR on s2; layer-1 GEMM kept as 4th-issued launch (ncu target)
    cudaEventRecord(evF, 0);
    cudaStreamWaitEvent(s2, evF, 0);

    k_init<<<NB, 256, 0, s2>>>();                                          // 1
    k_hist<<<ETB, 256, 0, s2>>>(ei);                                       // 2

    k_gemm_mma<DIN, true><<<dim3(MB, 1), 256>>>(x, W_nfc, b_nfc, gh,
                                                W_nfc, b_nfc, gh, NN);     // 3
    k_gemm_mma<H, false><<<dim3(MB, 2), 256>>>(gh, Wl1, bl1, gxl,
                                               Wr1, br1, gxr, NN);         // 4 (profiled)

    k_scan1<<<NB, 256, 0, s2>>>();
    k_scan2<<<1, 512, 0, s2>>>();
    k_scan3<<<NB, 256, 0, s2>>>();
    k_scatter<<<ETB, 256, 0, s2>>>(ei);
    cudaEventRecord(evJ, s2);

    cudaStreamWaitEvent(0, evJ, 0);

    k_node<false><<<NWB, 256>>>(att1, bias1, batch);

    k_gemm_mma<H, false><<<dim3(MB, 2), 256>>>(gh, Wl2, bl2, gxl, Wr2, br2, gxr, NN);
    k_node<true><<<NWB, 256>>>(att2, bias2, batch);

    k_head<<<NG, 32>>>(W_fc1, b_fc1, W_fc2, b_fc2, out);
}

// round 17
// speedup vs baseline: 1.2638x; 1.0023x over previous
#include <cuda_runtime.h>
#include <cuda_bf16.h>

#define NN 100000
#define NE 600000
#define ET (NE + NN)   // edges + self loops
#define H  128
#define NG 128
#define DIN 64
#define NB 391         // ceil(NN/256) scan blocks

// ---------------- scratch ----------------
__device__ float g_h[NN * H];
__device__ float g_xl[NN * H];
__device__ float g_xr[NN * H];
__device__ float g_pool[NG * H];
__device__ float g_cnt[NG];
__device__ int   g_deg[NN];
__device__ int   g_off[NN];
__device__ int   g_cursor[NN];
__device__ int   g_csrc[ET];
__device__ int   g_bsum[512];

// ---------------- helpers ----------------
__device__ __forceinline__ float lrelu(float v, float s) { return v > 0.f ? v : s * v; }

__device__ __forceinline__ void red_add_v4(float* p, float a, float b, float c, float d) {
    asm volatile("red.global.add.v4.f32 [%0], {%1,%2,%3,%4};"
                 :: "l"(p), "f"(a), "f"(b), "f"(c), "f"(d) : "memory");
}
__device__ __forceinline__ void red_add_f32(float* p, float a) {
    asm volatile("red.global.add.f32 [%0], %1;" :: "l"(p), "f"(a) : "memory");
}

// split two fp32 into packed bf16x2 hi + packed bf16x2 lo (v0 = even k)
__device__ __forceinline__ void bf16_split2(float v0, float v1, unsigned& hi, unsigned& lo) {
    __nv_bfloat16 h0 = __float2bfloat16(v0);
    __nv_bfloat16 h1 = __float2bfloat16(v1);
    __nv_bfloat16 l0 = __float2bfloat16(v0 - __bfloat162float(h0));
    __nv_bfloat16 l1 = __float2bfloat16(v1 - __bfloat162float(h1));
    __nv_bfloat162 hp = __halves2bfloat162(h0, h1);
    __nv_bfloat162 lp = __halves2bfloat162(l0, l1);
    hi = *reinterpret_cast<unsigned*>(&hp);
    lo = *reinterpret_cast<unsigned*>(&lp);
}
__device__ __forceinline__ void mma_bf16(float c[4],
        unsigned a0, unsigned a1, unsigned a2, unsigned a3,
        unsigned b0, unsigned b1) {
    asm volatile("mma.sync.aligned.m16n8k16.row.col.f32.bf16.bf16.f32 "
        "{%0,%1,%2,%3}, {%4,%5,%6,%7}, {%8,%9}, {%0,%1,%2,%3};"
        : "+f"(c[0]), "+f"(c[1]), "+f"(c[2]), "+f"(c[3])
        : "r"(a0), "r"(a1), "r"(a2), "r"(a3), "r"(b0), "r"(b1));
}
__device__ __forceinline__ void ldsm_x4(unsigned r[4], unsigned saddr) {
    asm volatile("ldmatrix.sync.aligned.m8n8.x4.shared.b16 {%0,%1,%2,%3}, [%4];"
                 : "=r"(r[0]), "=r"(r[1]), "=r"(r[2]), "=r"(r[3]) : "r"(saddr));
}

// ---------------- CSR build ----------------
__global__ void k_init() {
    int i = blockIdx.x * blockDim.x + threadIdx.x;
    if (i < NN) g_deg[i] = 0;
    if (i < NG * H) g_pool[i] = 0.f;
    if (i < NG) g_cnt[i] = 0.f;
}
__global__ void k_hist(const int* __restrict__ ei) {
    int e = blockIdx.x * blockDim.x + threadIdx.x;
    if (e >= ET) return;
    int d = (e < NE) ? ei[NE + e] : (e - NE);
    atomicAdd(&g_deg[d], 1);
}
__global__ void k_scan1() {
    __shared__ int sm[256];
    int t = threadIdx.x;
    int i = blockIdx.x * 256 + t;
    int v = (i < NN) ? g_deg[i] : 0;
    sm[t] = v;
    __syncthreads();
    for (int o = 1; o < 256; o <<= 1) {
        int add = (t >= o) ? sm[t - o] : 0;
        __syncthreads();
        sm[t] += add;
        __syncthreads();
    }
    if (i < NN) g_off[i] = sm[t] - v;
    if (t == 255) g_bsum[blockIdx.x] = sm[255];
}
__global__ void k_scan2() {
    __shared__ int sm[512];
    int t = threadIdx.x;
    int v = (t < NB) ? g_bsum[t] : 0;
    sm[t] = v;
    __syncthreads();
    for (int o = 1; o < 512; o <<= 1) {
        int add = (t >= o) ? sm[t - o] : 0;
        __syncthreads();
        sm[t] += add;
        __syncthreads();
    }
    if (t < NB) g_bsum[t] = sm[t] - v;
}
__global__ void k_scan3() {
    int i = blockIdx.x * 256 + threadIdx.x;
    if (i >= NN) return;
    int o = g_off[i] + g_bsum[blockIdx.x];
    g_off[i] = o;
    g_cursor[i] = o;
}
__global__ void k_scatter(const int* __restrict__ ei) {
    int e = blockIdx.x * blockDim.x + threadIdx.x;
    if (e >= ET) return;
    int s, d;
    if (e < NE) { s = ei[e]; d = ei[NE + e]; }
    else        { s = e - NE; d = s; }
    int pos = atomicAdd(&g_cursor[d], 1);
    g_csrc[pos] = s;
}

// ---------------- BF16 tensor-core GEMM (3xBF16, ldmatrix, A-prefetch pipeline) ----------------
// C = lrelu?(A[M,K] @ W[K,128] + bias); 256 thr = 8 warps, CTA 128x128, warp 32x64.
// A tile for the NEXT k-chunk is prefetched into registers during the MMA phase;
// W loads stay in-phase (64 KB, L1/L2-hot across CTAs).
#define APR 20
#define WPR2 20

template<int K, bool DO_LRELU>
__global__ __launch_bounds__(256, 2) void k_gemm_mma(
    const float* __restrict__ A,
    const float* __restrict__ B0, const float* __restrict__ bias0, float* __restrict__ C0,
    const float* __restrict__ B1, const float* __restrict__ bias1, float* __restrict__ C1,
    int M)
{
    const float* Bw   = blockIdx.y ? B1 : B0;
    const float* bias = blockIdx.y ? bias1 : bias0;
    float*       C    = blockIdx.y ? C1 : C0;

    __shared__ unsigned As_h[128][APR],  As_l[128][APR];    // 20480 B
    __shared__ unsigned Ws_h[128][WPR2], Ws_l[128][WPR2];   // 20480 B

    int tid  = threadIdx.x;
    int wid  = tid >> 5;
    int lane = tid & 31;
    int wr = wid & 3;            // m offset = 32*wr
    int wc = wid >> 2;           // n offset = 64*wc
    int row0 = blockIdx.x * 128;
    int g  = lane >> 2;
    int th = lane & 3;

    const float4 z4 = make_float4(0.f, 0.f, 0.f, 0.f);
    float acc[2][8][4] = {};

    // staging coords
    int a_r = tid >> 1;                  // A row (2 threads/row)
    int a_c = (tid & 1) * 16;            // k offset 0 or 16
    int w_col = tid & 127;               // W column
    int w_pg  = (tid >> 7) * 8;          // pair group 0 or 8
    int grow  = row0 + a_r;

    // ldmatrix lane->address precompute
    int a_row_l = wr * 32 + (lane & 15);
    int a_po    = (lane >> 4) << 2;
    unsigned a_h0 = (unsigned)__cvta_generic_to_shared(&As_h[a_row_l][a_po]);
    unsigned a_l0 = (unsigned)__cvta_generic_to_shared(&As_l[a_row_l][a_po]);
    int b_col_l = wc * 64 + (lane & 7) + ((lane >> 4) << 3);
    int b_po    = ((lane >> 3) & 1) << 2;
    unsigned b_h0 = (unsigned)__cvta_generic_to_shared(&Ws_h[b_col_l][b_po]);
    unsigned b_l0 = (unsigned)__cvta_generic_to_shared(&Ws_l[b_col_l][b_po]);

    // prologue: prefetch A chunk 0
    float4 pa[4];
#pragma unroll
    for (int q = 0; q < 4; q++)
        pa[q] = (grow < M) ? *(const float4*)&A[(long)grow * K + a_c + q * 4] : z4;

    for (int k0 = 0; k0 < K; k0 += 32) {
        // store prefetched A regs (hi/lo split)
#pragma unroll
        for (int q = 0; q < 4; q++) {
            int p = (a_c + q * 4) >> 1;
            bf16_split2(pa[q].x, pa[q].y, As_h[a_r][p],     As_l[a_r][p]);
            bf16_split2(pa[q].z, pa[q].w, As_h[a_r][p + 1], As_l[a_r][p + 1]);
        }
        // stage W column-major (L1/L2-hot)
#pragma unroll
        for (int q = 0; q < 8; q++) {
            int p = w_pg + q;
            float v0 = Bw[(long)(k0 + 2 * p    ) * 128 + w_col];
            float v1 = Bw[(long)(k0 + 2 * p + 1) * 128 + w_col];
            bf16_split2(v0, v1, Ws_h[w_col][p], Ws_l[w_col][p]);
        }
        __syncthreads();

        // prefetch next A chunk — LDG latency hidden under MMA phase
        int nk = k0 + 32;
        if (nk < K) {
#pragma unroll
            for (int q = 0; q < 4; q++)
                pa[q] = (grow < M) ? *(const float4*)&A[(long)grow * K + nk + a_c + q * 4] : z4;
        }

        // MMA phase: ldmatrix + 3xBF16 (interleaved per n-tile-pair)
#pragma unroll
        for (int pb = 0; pb < 16; pb += 8) {
            unsigned ah[2][4], al[2][4];
#pragma unroll
            for (int mt = 0; mt < 2; mt++) {
                unsigned off = (mt * 16 * APR + pb) * 4;
                ldsm_x4(ah[mt], a_h0 + off);
                ldsm_x4(al[mt], a_l0 + off);
            }
#pragma unroll
            for (int ntp = 0; ntp < 4; ntp++) {
                unsigned off = (ntp * 16 * WPR2 + pb) * 4;
                unsigned bh[4], bl[4];
                ldsm_x4(bh, b_h0 + off);
                ldsm_x4(bl, b_l0 + off);
#pragma unroll
                for (int hf = 0; hf < 2; hf++) {
                    int nt = ntp * 2 + hf;
                    unsigned b0h = bh[hf * 2], b1h = bh[hf * 2 + 1];
                    unsigned b0l = bl[hf * 2], b1l = bl[hf * 2 + 1];
#pragma unroll
                    for (int mt = 0; mt < 2; mt++) {
                        mma_bf16(acc[mt][nt], ah[mt][0], ah[mt][1], ah[mt][2], ah[mt][3], b0h, b1h);
                        mma_bf16(acc[mt][nt], al[mt][0], al[mt][1], al[mt][2], al[mt][3], b0h, b1h);
                        mma_bf16(acc[mt][nt], ah[mt][0], ah[mt][1], ah[mt][2], ah[mt][3], b0l, b1l);
                    }
                }
            }
        }
        __syncthreads();
    }

    // epilogue: bias + optional lrelu, float2 stores
#pragma unroll
    for (int nt = 0; nt < 8; nt++) {
        int col = wc * 64 + nt * 8 + 2 * th;
        float bx = bias[col], by = bias[col + 1];
#pragma unroll
        for (int mt = 0; mt < 2; mt++) {
            int r0 = row0 + wr * 32 + mt * 16 + g;
            float* c = acc[mt][nt];
            if (r0 < M) {
                float vx = c[0] + bx, vy = c[1] + by;
                if (DO_LRELU) { vx = lrelu(vx, 0.01f); vy = lrelu(vy, 0.01f); }
                *(float2*)&C[(long)r0 * 128 + col] = make_float2(vx, vy);
            }
            if (r0 + 8 < M) {
                float vx = c[2] + bx, vy = c[3] + by;
                if (DO_LRELU) { vx = lrelu(vx, 0.01f); vy = lrelu(vy, 0.01f); }
                *(float2*)&C[(long)(r0 + 8) * 128 + col] = make_float2(vx, vy);
            }
        }
    }
}

// ---------------- fused per-node edge kernel (CSR, no atomics) ----------------
template<bool POOL>
__global__ void k_node(const float* __restrict__ att, const float* __restrict__ bias,
                       const int* __restrict__ batch) {
    int node = (blockIdx.x * blockDim.x + threadIdx.x) >> 5;
    int lane = threadIdx.x & 31;
    if (node >= NN) return;

    int start = g_off[node];
    int deg   = g_deg[node];

    float4 xr4 = *(const float4*)&g_xr[node * H + lane * 4];
    float4 t4  = *(const float4*)&att[lane * 4];

    float4 acc = make_float4(0.f, 0.f, 0.f, 0.f);
    float denom = 0.f;

    for (int base = 0; base < deg; base += 32) {
        int m = min(32, deg - base);
        int s_l = (lane < m) ? g_csrc[start + base + lane] : 0;
#pragma unroll 4
        for (int j = 0; j < m; j++) {
            int s = __shfl_sync(0xffffffffu, s_l, j);
            float4 xl4 = *(const float4*)&g_xl[s * H + lane * 4];
            float e = t4.x * lrelu(xl4.x + xr4.x, 0.2f)
                    + t4.y * lrelu(xl4.y + xr4.y, 0.2f)
                    + t4.z * lrelu(xl4.z + xr4.z, 0.2f)
                    + t4.w * lrelu(xl4.w + xr4.w, 0.2f);
#pragma unroll
            for (int o = 16; o > 0; o >>= 1) e += __shfl_xor_sync(0xffffffffu, e, o);
            float a = __expf(e);
            denom += a;
            acc.x += a * xl4.x; acc.y += a * xl4.y;
            acc.z += a * xl4.z; acc.w += a * xl4.w;
        }
    }

    float inv = 1.0f / denom;        // self-loop guarantees denom > 0
    float4 b4 = *(const float4*)&bias[lane * 4];
    float vx = lrelu(acc.x * inv + b4.x, 0.01f);
    float vy = lrelu(acc.y * inv + b4.y, 0.01f);
    float vz = lrelu(acc.z * inv + b4.z, 0.01f);
    float vw = lrelu(acc.w * inv + b4.w, 0.01f);

    if (POOL) {
        int g = batch[node];
        red_add_v4(&g_pool[g * H + lane * 4], vx, vy, vz, vw);
        if (lane == 0) red_add_f32(&g_cnt[g], 1.0f);
    } else {
        *(float4*)&g_h[node * H + lane * 4] = make_float4(vx, vy, vz, vw);
    }
}

// head
__global__ void k_head(const float* __restrict__ W1, const float* __restrict__ b1,
                       const float* __restrict__ W2, const float* __restrict__ b2,
                       float* __restrict__ out) {
    int g = blockIdx.x;
    int t = threadIdx.x;
    __shared__ float hg[H];
    __shared__ float z[32];
    float c = fmaxf(g_cnt[g], 1.0f);
    for (int i = t; i < H; i += 32) hg[i] = g_pool[g * H + i] / c;
    __syncthreads();
    float acc = b1[t];
#pragma unroll 8
    for (int k = 0; k < H; k++) acc += hg[k] * W1[k * 32 + t];
    z[t] = lrelu(acc, 0.01f);
    __syncthreads();
    if (t < 16) {
        float o = b2[t];
#pragma unroll
        for (int k = 0; k < 32; k++) o += z[k] * W2[k * 16 + t];
        out[g * 16 + t] = o;
    }
}

// ---------------- launch ----------------
extern "C" void kernel_launch(void* const* d_in, const int* in_sizes, int n_in,
                              void* d_out, int out_size) {
    const float* x      = (const float*)d_in[0];
    const int*   ei     = (const int*)d_in[1];
    const int*   batch  = (const int*)d_in[2];
    const float* W_nfc  = (const float*)d_in[3];
    const float* b_nfc  = (const float*)d_in[4];
    const float* Wl1    = (const float*)d_in[5];
    const float* bl1    = (const float*)d_in[6];
    const float* Wr1    = (const float*)d_in[7];
    const float* br1    = (const float*)d_in[8];
    const float* att1   = (const float*)d_in[9];
    const float* bias1  = (const float*)d_in[10];
    const float* Wl2    = (const float*)d_in[11];
    const float* bl2    = (const float*)d_in[12];
    const float* Wr2    = (const float*)d_in[13];
    const float* br2    = (const float*)d_in[14];
    const float* att2   = (const float*)d_in[15];
    const float* bias2  = (const float*)d_in[16];
    const float* W_fc1  = (const float*)d_in[17];
    const float* b_fc1  = (const float*)d_in[18];
    const float* W_fc2  = (const float*)d_in[19];
    const float* b_fc2  = (const float*)d_in[20];
    float*       out    = (float*)d_out;

    float* gh  = nullptr; cudaGetSymbolAddress((void**)&gh,  g_h);
    float* gxl = nullptr; cudaGetSymbolAddress((void**)&gxl, g_xl);
    float* gxr = nullptr; cudaGetSymbolAddress((void**)&gxr, g_xr);

    static cudaStream_t s2 = nullptr;
    static cudaEvent_t  evF = nullptr, evJ = nullptr;
    if (s2 == nullptr) {
        cudaStreamCreateWithFlags(&s2, cudaStreamNonBlocking);
        cudaEventCreateWithFlags(&evF, cudaEventDisableTiming);
        cudaEventCreateWithFlags(&evJ, cudaEventDisableTiming);
    }

    const int MB  = (NN + 127) / 128;             // 782
    const int ETB = (ET + 255) / 256;
    const int NWB = (NN * 32 + 255) / 256;

    // fork for CSR on s2; layer-1 GEMM kept as 4th-issued launch (ncu target)
    cudaEventRecord(evF, 0);
    cudaStreamWaitEvent(s2, evF, 0);

    k_init<<<NB, 256, 0, s2>>>();                                          // 1
    k_hist<<<ETB, 256, 0, s2>>>(ei);                                       // 2

    k_gemm_mma<DIN, true><<<dim3(MB, 1), 256>>>(x, W_nfc, b_nfc, gh,
                                                W_nfc, b_nfc, gh, NN);     // 3
    k_gemm_mma<H, false><<<dim3(MB, 2), 256>>>(gh, Wl1, bl1, gxl,
                                               Wr1, br1, gxr, NN);         // 4 (profiled)

    k_scan1<<<NB, 256, 0, s2>>>();
    k_scan2<<<1, 512, 0, s2>>>();
    k_scan3<<<NB, 256, 0, s2>>>();
    k_scatter<<<ETB, 256, 0, s2>>>(ei);
    cudaEventRecord(evJ, s2);

    cudaStreamWaitEvent(0, evJ, 0);

    k_node<false><<<NWB, 256>>>(att1, bias1, batch);

    k_gemm_mma<H, false><<<dim3(MB, 2), 256>>>(gh, Wl2, bl2, gxl, Wr2, br2, gxr, NN);
    k_node<true><<<NWB, 256>>>(att2, bias2, batch);

    k_head<<<NG, 32>>>(W_fc1, b_fc1, W_fc2, b_fc2, out);
}